// round 5
// baseline (speedup 1.0000x reference)
#include <cuda_runtime.h>
#include <cuda_fp16.h>
#include <math.h>
#include <stdint.h>

#define BB 16
#define NN 784
#define CC 384
#define HH 8
#define HD 48
#define INNER 1152
#define MM (BB*NN)          // 12544
#define EPSV 1e-5f

// ---------------- scratch ----------------
__device__ __half g_xh[(size_t)MM * CC];
__device__ __half g_wqh[(size_t)INNER * CC];
__device__ __half g_wph[(size_t)CC * CC];
__device__ __half g_yh[(size_t)MM * INNER];     // qkv pre-norm, fp16 (28.9 MB)
__device__ float  g_sc1[INNER];
__device__ float  g_sh1[INNER];
__device__ __half g_ohsh[(size_t)MM * CC];      // hardswish(attn out), fp16
__device__ float  g_z[(size_t)MM * CC];         // proj pre-norm, fp32
__device__ float  g_sc2[CC];
__device__ float  g_sh2[CC];

// ---------------- helpers ----------------
__device__ __forceinline__ uint32_t pack2(float a, float b) {
    __half2 h = __floats2half2_rn(a, b);
    return *reinterpret_cast<uint32_t*>(&h);
}
__device__ __forceinline__ uint32_t smem_u32(const void* p) {
    return (uint32_t)__cvta_generic_to_shared(p);
}
__device__ __forceinline__ void mma_f16(float* c,
        uint32_t a0, uint32_t a1, uint32_t a2, uint32_t a3,
        uint32_t b0, uint32_t b1) {
    asm volatile("mma.sync.aligned.m16n8k16.row.col.f32.f16.f16.f32 "
                 "{%0,%1,%2,%3},{%4,%5,%6,%7},{%8,%9},{%0,%1,%2,%3};"
                 : "+f"(c[0]), "+f"(c[1]), "+f"(c[2]), "+f"(c[3])
                 : "r"(a0), "r"(a1), "r"(a2), "r"(a3), "r"(b0), "r"(b1));
}
__device__ __forceinline__ float fexp2f(float y) {
    float r = y + 12582912.0f;
    float i = r - 12582912.0f;
    float f = y - i;
    int   e = __float_as_int(r) << 23;
    float p = 1.5403530393e-4f;
    p = fmaf(p, f, 1.3333558146e-3f);
    p = fmaf(p, f, 9.6181291076e-3f);
    p = fmaf(p, f, 5.5504108664e-2f);
    p = fmaf(p, f, 2.4022650696e-1f);
    p = fmaf(p, f, 6.9314718056e-1f);
    p = fmaf(p, f, 1.0f);
    return __int_as_float(__float_as_int(p) + e);
}
__device__ __forceinline__ float hswish(float v) {
    return v * fminf(fmaxf(v + 3.f, 0.f), 6.f) * (1.0f/6.0f);
}

// ---------------- fp32 -> fp16 convert ----------------
__global__ __launch_bounds__(256) void f2h(const float* __restrict__ in,
                                           __half* __restrict__ out, int n4) {
    int i = blockIdx.x * 256 + threadIdx.x;
    if (i < n4) {
        float4 v = ((const float4*)in)[i];
        __half2* o = (__half2*)out;
        o[2*i]   = __floats2half2_rn(v.x, v.y);
        o[2*i+1] = __floats2half2_rn(v.z, v.w);
    }
}

// ---------------- cp.async pipelined fp16 GEMM NT (K=384) ----------------
template<int OUTH>
__global__ __launch_bounds__(256) void gemm_cp(const __half* __restrict__ A,
                                               const __half* __restrict__ Bw,
                                               void* __restrict__ C, int Nn) {
    extern __shared__ __half hs[];          // [3][2][128*40]
    const int STG = 128*40;
    int t = threadIdx.x;
    int w = t >> 5, L = t & 31;
    int g = L >> 2, c = L & 3;
    int wm = w & 3, wn = w >> 2;
    int m0 = blockIdx.y * 128, n0 = blockIdx.x * 128;

    int id0 = t, id1 = t + 256;
    int ra0 = id0 >> 2, oa0 = (id0 & 3) * 8;
    int ra1 = id1 >> 2, oa1 = (id1 & 3) * 8;
    const __half* Ap0 = A  + (size_t)(m0 + ra0) * 384 + oa0;
    const __half* Ap1 = A  + (size_t)(m0 + ra1) * 384 + oa1;
    const __half* Bp0 = Bw + (size_t)(n0 + ra0) * 384 + oa0;
    const __half* Bp1 = Bw + (size_t)(n0 + ra1) * 384 + oa1;

    uint32_t dA0 = smem_u32(&hs[ra0*40 + oa0]);
    uint32_t dA1 = smem_u32(&hs[ra1*40 + oa1]);
    uint32_t dB0 = smem_u32(&hs[STG + ra0*40 + oa0]);
    uint32_t dB1 = smem_u32(&hs[STG + ra1*40 + oa1]);

    #define ISSUE(st, kc) { \
        int ko = (kc) * 32; uint32_t so = (st) * (2*STG*2); \
        asm volatile("cp.async.ca.shared.global [%0], [%1], 16;" :: "r"(dA0+so), "l"(Ap0+ko)); \
        asm volatile("cp.async.ca.shared.global [%0], [%1], 16;" :: "r"(dA1+so), "l"(Ap1+ko)); \
        asm volatile("cp.async.ca.shared.global [%0], [%1], 16;" :: "r"(dB0+so), "l"(Bp0+ko)); \
        asm volatile("cp.async.ca.shared.global [%0], [%1], 16;" :: "r"(dB1+so), "l"(Bp1+ko)); \
        asm volatile("cp.async.commit_group;"); }

    float acc[2][8][4] = {};
    ISSUE(0, 0); ISSUE(1, 1);

    for (int kc = 0; kc < 12; kc++) {
        if (kc < 11) asm volatile("cp.async.wait_group 1;");
        else         asm volatile("cp.async.wait_group 0;");
        __syncthreads();
        if (kc + 2 < 12) { int st = (kc+2)%3; ISSUE(st, kc+2); }
        const uint32_t* swA = (const uint32_t*)&hs[(kc%3)*2*STG];
        const uint32_t* swB = (const uint32_t*)&hs[(kc%3)*2*STG + STG];
        #pragma unroll
        for (int ks = 0; ks < 2; ks++) {
            int kf = ks * 8;
            uint32_t b0[8], b1[8];
            #pragma unroll
            for (int nb = 0; nb < 8; nb++) {
                int br = (wn*64 + nb*8 + g)*20 + kf;
                b0[nb] = swB[br + c];
                b1[nb] = swB[br + c + 4];
            }
            #pragma unroll
            for (int i = 0; i < 2; i++) {
                int ar = (wm*32 + i*16 + g)*20 + kf;
                uint32_t a0 = swA[ar + c],     a1 = swA[ar + 8*20 + c];
                uint32_t a2 = swA[ar + c + 4], a3 = swA[ar + 8*20 + c + 4];
                #pragma unroll
                for (int nb = 0; nb < 8; nb++)
                    mma_f16(acc[i][nb], a0, a1, a2, a3, b0[nb], b1[nb]);
            }
        }
    }
    #undef ISSUE

    #pragma unroll
    for (int i = 0; i < 2; i++) {
        int row = m0 + wm*32 + i*16 + g;
        #pragma unroll
        for (int nb = 0; nb < 8; nb++) {
            int col = n0 + wn*64 + nb*8 + 2*c;
            if (OUTH) {
                __half2* Ch = (__half2*)C;
                Ch[((size_t)row*Nn + col) >> 1]     = __floats2half2_rn(acc[i][nb][0], acc[i][nb][1]);
                Ch[((size_t)(row+8)*Nn + col) >> 1] = __floats2half2_rn(acc[i][nb][2], acc[i][nb][3]);
            } else {
                float* Cf = (float*)C;
                *(float2*)(Cf + (size_t)row*Nn + col)     = make_float2(acc[i][nb][0], acc[i][nb][1]);
                *(float2*)(Cf + (size_t)(row+8)*Nn + col) = make_float2(acc[i][nb][2], acc[i][nb][3]);
            }
        }
    }
}

// ---------------- column stats, fp16 input ----------------
__global__ __launch_bounds__(256) void colstats_h(const __half* __restrict__ Y, int Ncol,
                                                  const float* __restrict__ gamma,
                                                  const float* __restrict__ beta,
                                                  float* __restrict__ scOut,
                                                  float* __restrict__ shOut) {
    int lc = threadIdx.x & 31;
    int rg = threadIdx.x >> 5;
    int cp = blockIdx.x * 32 + lc;
    const __half2* Y2 = (const __half2*)Y;
    int stride = Ncol >> 1;
    float sx = 0.f, sx2 = 0.f, sy = 0.f, sy2 = 0.f;
    for (int r = rg; r < MM; r += 8) {
        float2 f = __half22float2(Y2[(size_t)r * stride + cp]);
        sx += f.x; sx2 += f.x*f.x; sy += f.y; sy2 += f.y*f.y;
    }
    __shared__ float sA[8][32], sB[8][32], sC2[8][32], sD[8][32];
    sA[rg][lc] = sx; sB[rg][lc] = sx2; sC2[rg][lc] = sy; sD[rg][lc] = sy2;
    __syncthreads();
    if (rg == 0) {
        #pragma unroll
        for (int gg = 1; gg < 8; gg++) {
            sx += sA[gg][lc]; sx2 += sB[gg][lc]; sy += sC2[gg][lc]; sy2 += sD[gg][lc];
        }
        int c0 = 2*cp, c1 = 2*cp + 1;
        float m0 = sx * (1.0f/MM), m1 = sy * (1.0f/MM);
        float v0 = sx2 * (1.0f/MM) - m0*m0;
        float v1 = sy2 * (1.0f/MM) - m1*m1;
        float s0 = gamma[c0] * rsqrtf(v0 + EPSV);
        float s1 = gamma[c1] * rsqrtf(v1 + EPSV);
        scOut[c0] = s0; shOut[c0] = beta[c0] - m0*s0;
        scOut[c1] = s1; shOut[c1] = beta[c1] - m1*s1;
    }
}

// ---------------- column stats, fp32 input ----------------
__global__ __launch_bounds__(256) void colstats_f(const float* __restrict__ Y, int Ncol,
                                                  const float* __restrict__ gamma,
                                                  const float* __restrict__ beta,
                                                  float* __restrict__ scOut,
                                                  float* __restrict__ shOut) {
    int lc = threadIdx.x & 31;
    int rg = threadIdx.x >> 5;
    int c  = blockIdx.x * 32 + lc;
    float s = 0.f, s2 = 0.f;
    for (int r = rg; r < MM; r += 8) {
        float v = Y[(size_t)r * Ncol + c];
        s += v; s2 += v * v;
    }
    __shared__ float sh[8][32], sh2[8][32];
    sh[rg][lc] = s; sh2[rg][lc] = s2;
    __syncthreads();
    if (rg == 0) {
        #pragma unroll
        for (int gg = 1; gg < 8; gg++) { s += sh[gg][lc]; s2 += sh2[gg][lc]; }
        float mean = s * (1.0f / MM);
        float var  = s2 * (1.0f / MM) - mean * mean;
        float sc   = gamma[c] * rsqrtf(var + EPSV);
        scOut[c] = sc;
        shOut[c] = beta[c] - mean * sc;
    }
}

// ---------------- fused attention ----------------
__global__ __launch_bounds__(224, 2) void attn_kernel(const __half* __restrict__ Y,
                                                      const float* __restrict__ biases,
                                                      const float* __restrict__ sc1,
                                                      const float* __restrict__ sh1,
                                                      __half* __restrict__ Ohs) {
    extern __shared__ uint32_t sm[];
    float* smf = (float*)sm;
    const int QW = 0, KW = 3136, PW = 4928, VW = 8960;
    float* biasRow = smf + 10688;
    float* lsumf   = smf + 11472;
    float* nscp    = smf + 11584;
    float* nshp    = smf + 11728;
    __half* smh = (__half*)sm;

    int t = threadIdx.x;
    int w = t >> 5, L = t & 31;
    int g = L >> 2, c = L & 3;
    int m0l = w * 16;
    int bh = blockIdx.y;
    int b = bh >> 3, h = bh & 7;
    int q0 = blockIdx.x * 112;

    if (t < 144) {
        int p = t / 48, d = t % 48;
        nscp[t] = sc1[p * CC + h * HD + d];
        nshp[t] = sh1[p * CC + h * HD + d];
    }
    for (int i = t; i < NN; i += 224) biasRow[i] = biases[h * NN + i] * 1.4426950408889634f;
    if (t < 112) lsumf[t] = 0.f;
    __syncthreads();

    #pragma unroll
    for (int j = 0; j < 12; j++) {
        int i = t + 224 * j;
        int r = i / 24, dp = i % 24;
        float2 f = __half22float2(*(const __half2*)(Y + (size_t)(b*NN + q0 + r) * INNER + h*HD + 2*dp));
        sm[QW + r*28 + dp] = pack2(f.x * nscp[2*dp] + nshp[2*dp],
                                   f.y * nscp[2*dp+1] + nshp[2*dp+1]);
    }

    int qr0 = q0 + m0l + g, qr1 = qr0 + 8;
    int xi0 = qr0 / 28, yi0 = qr0 - xi0 * 28;
    int xi1 = qr1 / 28, yi1 = qr1 - xi1 * 28;

    const float cs = 0.14433756729740643f * 1.4426950408889634f;
    float Oc[6][4] = {};

    for (int kt = 0; kt < 13; kt++) {
        int k0 = kt * 64;
        __syncthreads();
        #pragma unroll
        for (int j = 0; j < 7; j++) {
            int i = t + 224 * j;
            if (i < 1536) {
                int r = i / 24, dp = i % 24;
                int n = k0 + r;
                float2 f = make_float2(0.f, 0.f);
                if (n < NN) f = __half22float2(*(const __half2*)(Y + (size_t)(b*NN + n) * INNER + 384 + h*HD + 2*dp));
                sm[KW + r*28 + dp] = pack2(f.x * nscp[48+2*dp] + nshp[48+2*dp],
                                           f.y * nscp[48+2*dp+1] + nshp[48+2*dp+1]);
            }
        }
        #pragma unroll
        for (int j = 0; j < 7; j++) {
            int i = t + 224 * j;
            if (i < 1536) {
                int dp = i / 64, r = i % 64;
                int n = k0 + r;
                float2 f = make_float2(0.f, 0.f);
                if (n < NN) f = __half22float2(*(const __half2*)(Y + (size_t)(b*NN + n) * INNER + 768 + h*HD + 2*dp));
                smh[VW*2 + (2*dp)*72 + r]   = __float2half_rn(f.x * nscp[96+2*dp] + nshp[96+2*dp]);
                smh[VW*2 + (2*dp+1)*72 + r] = __float2half_rn(f.y * nscp[96+2*dp+1] + nshp[96+2*dp+1]);
            }
        }
        __syncthreads();

        float Sc[8][4] = {};
        #pragma unroll
        for (int ks = 0; ks < 3; ks++) {
            int kf = ks * 8;
            int ar = QW + (m0l + g)*28 + kf;
            uint32_t a0 = sm[ar + c],     a1 = sm[ar + 8*28 + c];
            uint32_t a2 = sm[ar + c + 4], a3 = sm[ar + 8*28 + c + 4];
            #pragma unroll
            for (int nb = 0; nb < 8; nb++) {
                int br = KW + (nb*8 + g)*28 + kf;
                mma_f16(Sc[nb], a0, a1, a2, a3, sm[br + c], sm[br + c + 4]);
            }
        }

        float rs0 = 0.f, rs1 = 0.f;
        #pragma unroll
        for (int nb = 0; nb < 8; nb++) {
            int col0 = nb*8 + 2*c;
            int kj = k0 + col0;
            float p0 = 0.f, p1 = 0.f, p2 = 0.f, p3 = 0.f;
            if (kj < NN) {
                int xj = kj / 28, yj = kj - xj * 28;
                float b0v = biasRow[abs(xi0 - xj)*28 + abs(yi0 - yj)];
                float b2v = biasRow[abs(xi1 - xj)*28 + abs(yi1 - yj)];
                p0 = fexp2f(fmaf(Sc[nb][0], cs, b0v));
                p2 = fexp2f(fmaf(Sc[nb][2], cs, b2v));
            }
            if (kj + 1 < NN) {
                int kj1 = kj + 1;
                int xj = kj1 / 28, yj = kj1 - xj * 28;
                float b1v = biasRow[abs(xi0 - xj)*28 + abs(yi0 - yj)];
                float b3v = biasRow[abs(xi1 - xj)*28 + abs(yi1 - yj)];
                p1 = fexp2f(fmaf(Sc[nb][1], cs, b1v));
                p3 = fexp2f(fmaf(Sc[nb][3], cs, b3v));
            }
            rs0 += p0 + p1; rs1 += p2 + p3;
            sm[PW + (m0l + g)*36 + nb*4 + c]     = pack2(p0, p1);
            sm[PW + (m0l + 8 + g)*36 + nb*4 + c] = pack2(p2, p3);
        }
        rs0 += __shfl_xor_sync(0xffffffffu, rs0, 1);
        rs0 += __shfl_xor_sync(0xffffffffu, rs0, 2);
        rs1 += __shfl_xor_sync(0xffffffffu, rs1, 1);
        rs1 += __shfl_xor_sync(0xffffffffu, rs1, 2);
        if (c == 0) {
            lsumf[m0l + g]     += rs0;
            lsumf[m0l + 8 + g] += rs1;
        }
        __syncwarp();

        #pragma unroll
        for (int ks = 0; ks < 4; ks++) {
            int kf = ks * 8;
            int ar = PW + (m0l + g)*36 + kf;
            uint32_t a0 = sm[ar + c],     a1 = sm[ar + 8*36 + c];
            uint32_t a2 = sm[ar + c + 4], a3 = sm[ar + 8*36 + c + 4];
            #pragma unroll
            for (int nb = 0; nb < 6; nb++) {
                int br = VW + (nb*8 + g)*36 + kf;
                mma_f16(Oc[nb], a0, a1, a2, a3, sm[br + c], sm[br + c + 4]);
            }
        }
    }

    __syncwarp();
    float inv0 = 1.0f / lsumf[m0l + g];
    float inv1 = 1.0f / lsumf[m0l + 8 + g];
    int n0g = q0 + m0l + g, n1g = n0g + 8;
    __half2* O2 = (__half2*)Ohs;
    #pragma unroll
    for (int nb = 0; nb < 6; nb++) {
        int d = h*HD + nb*8 + 2*c;
        O2[((size_t)(b*NN + n0g)*CC + d) >> 1] =
            __floats2half2_rn(hswish(Oc[nb][0]*inv0), hswish(Oc[nb][1]*inv0));
        O2[((size_t)(b*NN + n1g)*CC + d) >> 1] =
            __floats2half2_rn(hswish(Oc[nb][2]*inv1), hswish(Oc[nb][3]*inv1));
    }
}

// ---------------- final BN apply ----------------
__global__ __launch_bounds__(256) void apply_bn(const float* __restrict__ Z,
                                                const float* __restrict__ sc,
                                                const float* __restrict__ sh,
                                                float* __restrict__ out) {
    size_t base = ((size_t)blockIdx.x * 256 + threadIdx.x) * 4;
    if (base < (size_t)MM * CC) {
        float4 z = *(const float4*)(Z + base);
        int c = (int)(base % CC);
        float4 o;
        o.x = z.x * sc[c+0] + sh[c+0];
        o.y = z.y * sc[c+1] + sh[c+1];
        o.z = z.z * sc[c+2] + sh[c+2];
        o.w = z.w * sc[c+3] + sh[c+3];
        *(float4*)(out + base) = o;
    }
}

extern "C" void kernel_launch(void* const* d_in, const int* in_sizes, int n_in,
                              void* d_out, int out_size) {
    const float* x      = (const float*)d_in[0];
    const float* Wqkv   = (const float*)d_in[1];
    const float* g1     = (const float*)d_in[2];
    const float* b1     = (const float*)d_in[3];
    const float* Wproj  = (const float*)d_in[4];
    const float* g2     = (const float*)d_in[5];
    const float* b2     = (const float*)d_in[6];
    const float* biases = (const float*)d_in[7];
    float* out = (float*)d_out;

    __half *xh, *wqh, *wph, *yh, *ohsh;
    float *sc1, *sh1, *zp, *sc2, *sh2;
    cudaGetSymbolAddress((void**)&xh,   g_xh);
    cudaGetSymbolAddress((void**)&wqh,  g_wqh);
    cudaGetSymbolAddress((void**)&wph,  g_wph);
    cudaGetSymbolAddress((void**)&yh,   g_yh);
    cudaGetSymbolAddress((void**)&sc1,  g_sc1);
    cudaGetSymbolAddress((void**)&sh1,  g_sh1);
    cudaGetSymbolAddress((void**)&ohsh, g_ohsh);
    cudaGetSymbolAddress((void**)&zp,   g_z);
    cudaGetSymbolAddress((void**)&sc2,  g_sc2);
    cudaGetSymbolAddress((void**)&sh2,  g_sh2);

    cudaFuncSetAttribute(gemm_cp<1>, cudaFuncAttributeMaxDynamicSharedMemorySize, 61440);
    cudaFuncSetAttribute(gemm_cp<0>, cudaFuncAttributeMaxDynamicSharedMemorySize, 61440);
    cudaFuncSetAttribute(attn_kernel, cudaFuncAttributeMaxDynamicSharedMemorySize, 47488);

    f2h<<<(MM*CC/4 + 255)/256, 256>>>(x, xh, MM*CC/4);
    f2h<<<(INNER*CC/4 + 255)/256, 256>>>(Wqkv, wqh, INNER*CC/4);
    f2h<<<(CC*CC/4 + 255)/256, 256>>>(Wproj, wph, CC*CC/4);

    gemm_cp<1><<<dim3(INNER/128, MM/128), 256, 61440>>>(xh, wqh, yh, INNER);
    colstats_h<<<INNER/64, 256>>>(yh, INNER, g1, b1, sc1, sh1);
    attn_kernel<<<dim3(7, BB*HH), 224, 47488>>>(yh, biases, sc1, sh1, ohsh);
    gemm_cp<0><<<dim3(CC/128, MM/128), 256, 61440>>>(ohsh, wph, zp, CC);
    colstats_f<<<CC/32, 256>>>(zp, CC, g2, b2, sc2, sh2);
    apply_bn<<<(MM*CC/4 + 255)/256, 256>>>(zp, sc2, sh2, out);
}

// round 6
// speedup vs baseline: 1.7858x; 1.7858x over previous
#include <cuda_runtime.h>
#include <cuda_fp16.h>
#include <math.h>
#include <stdint.h>

#define BB 16
#define NN 784
#define CC 384
#define HH 8
#define HD 48
#define INNER 1152
#define MM (BB*NN)          // 12544
#define EPSV 1e-5f

// ---------------- scratch ----------------
__device__ __half g_xh[(size_t)MM * CC];
__device__ __half g_wqh[(size_t)INNER * CC];
__device__ __half g_wph[(size_t)CC * CC];
__device__ __half g_yh[(size_t)MM * INNER];     // qkv pre-norm, fp16 (28.9 MB)
__device__ float  g_sc1[INNER];
__device__ float  g_sh1[INNER];
__device__ __half g_ohsh[(size_t)MM * CC];      // hardswish(attn out), fp16
__device__ float  g_z[(size_t)MM * CC];         // proj pre-norm, fp32
__device__ float  g_sc2[CC];
__device__ float  g_sh2[CC];

// ---------------- helpers ----------------
__device__ __forceinline__ uint32_t pack2(float a, float b) {
    __half2 h = __floats2half2_rn(a, b);
    return *reinterpret_cast<uint32_t*>(&h);
}
__device__ __forceinline__ uint32_t smem_u32(const void* p) {
    return (uint32_t)__cvta_generic_to_shared(p);
}
__device__ __forceinline__ void mma_f16(float* c,
        uint32_t a0, uint32_t a1, uint32_t a2, uint32_t a3,
        uint32_t b0, uint32_t b1) {
    asm volatile("mma.sync.aligned.m16n8k16.row.col.f32.f16.f16.f32 "
                 "{%0,%1,%2,%3},{%4,%5,%6,%7},{%8,%9},{%0,%1,%2,%3};"
                 : "+f"(c[0]), "+f"(c[1]), "+f"(c[2]), "+f"(c[3])
                 : "r"(a0), "r"(a1), "r"(a2), "r"(a3), "r"(b0), "r"(b1));
}
__device__ __forceinline__ void ldsm4(uint32_t& r0, uint32_t& r1, uint32_t& r2, uint32_t& r3, uint32_t a) {
    asm volatile("ldmatrix.sync.aligned.m8n8.x4.shared.b16 {%0,%1,%2,%3}, [%4];"
                 : "=r"(r0),"=r"(r1),"=r"(r2),"=r"(r3) : "r"(a));
}
__device__ __forceinline__ void ldsm4t(uint32_t& r0, uint32_t& r1, uint32_t& r2, uint32_t& r3, uint32_t a) {
    asm volatile("ldmatrix.sync.aligned.m8n8.x4.trans.shared.b16 {%0,%1,%2,%3}, [%4];"
                 : "=r"(r0),"=r"(r1),"=r"(r2),"=r"(r3) : "r"(a));
}
__device__ __forceinline__ float fexp2f(float y) {
    float r = y + 12582912.0f;
    float i = r - 12582912.0f;
    float f = y - i;
    int   e = __float_as_int(r) << 23;
    float p = 1.5403530393e-4f;
    p = fmaf(p, f, 1.3333558146e-3f);
    p = fmaf(p, f, 9.6181291076e-3f);
    p = fmaf(p, f, 5.5504108664e-2f);
    p = fmaf(p, f, 2.4022650696e-1f);
    p = fmaf(p, f, 6.9314718056e-1f);
    p = fmaf(p, f, 1.0f);
    return __int_as_float(__float_as_int(p) + e);
}
__device__ __forceinline__ float hswish(float v) {
    return v * fminf(fmaxf(v + 3.f, 0.f), 6.f) * (1.0f/6.0f);
}

// ---------------- fp32 -> fp16 convert ----------------
__global__ __launch_bounds__(256) void f2h(const float* __restrict__ in,
                                           __half* __restrict__ out, int n4) {
    int i = blockIdx.x * 256 + threadIdx.x;
    if (i < n4) {
        float4 v = ((const float4*)in)[i];
        __half2* o = (__half2*)out;
        o[2*i]   = __floats2half2_rn(v.x, v.y);
        o[2*i+1] = __floats2half2_rn(v.z, v.w);
    }
}

// ---------------- cp.async pipelined fp16 GEMM NT (K=384), ldmatrix frags ----------------
template<int OUTH>
__global__ __launch_bounds__(256) void gemm_cp(const __half* __restrict__ A,
                                               const __half* __restrict__ Bw,
                                               void* __restrict__ C, int Nn) {
    extern __shared__ __half hs[];          // [3][2][128*40]
    const int STG = 128*40;
    int t = threadIdx.x;
    int w = t >> 5, L = t & 31;
    int g = L >> 2, c = L & 3;
    int wm = w & 3, wn = w >> 2;
    int m0 = blockIdx.y * 128, n0 = blockIdx.x * 128;

    int id0 = t, id1 = t + 256;
    int ra0 = id0 >> 2, oa0 = (id0 & 3) * 8;
    int ra1 = id1 >> 2, oa1 = (id1 & 3) * 8;
    const __half* Ap0 = A  + (size_t)(m0 + ra0) * 384 + oa0;
    const __half* Ap1 = A  + (size_t)(m0 + ra1) * 384 + oa1;
    const __half* Bp0 = Bw + (size_t)(n0 + ra0) * 384 + oa0;
    const __half* Bp1 = Bw + (size_t)(n0 + ra1) * 384 + oa1;

    uint32_t base = smem_u32(hs);
    uint32_t dA0 = base + (ra0*40 + oa0)*2;
    uint32_t dA1 = base + (ra1*40 + oa1)*2;
    uint32_t dB0 = base + (STG + ra0*40 + oa0)*2;
    uint32_t dB1 = base + (STG + ra1*40 + oa1)*2;

    // ldmatrix lane addressing
    int r8 = L & 7, sel = L >> 3;
    uint32_t aAddr = base + ((wm*32 + (L & 15))*40 + (L >> 4)*8)*2;    // + i*16*80 + ks*32 + stage
    uint32_t bAddr = base + STG*2 + ((wn*64 + (sel>>1)*8 + r8)*40 + (sel&1)*8)*2; // + nbp*16*80 + ks*32

    #define ISSUE(st, kc) { \
        int ko = (kc) * 32; uint32_t so = (st) * (2*STG*2); \
        asm volatile("cp.async.ca.shared.global [%0], [%1], 16;" :: "r"(dA0+so), "l"(Ap0+ko)); \
        asm volatile("cp.async.ca.shared.global [%0], [%1], 16;" :: "r"(dA1+so), "l"(Ap1+ko)); \
        asm volatile("cp.async.ca.shared.global [%0], [%1], 16;" :: "r"(dB0+so), "l"(Bp0+ko)); \
        asm volatile("cp.async.ca.shared.global [%0], [%1], 16;" :: "r"(dB1+so), "l"(Bp1+ko)); \
        asm volatile("cp.async.commit_group;"); }

    float acc[2][8][4] = {};
    ISSUE(0, 0); ISSUE(1, 1);

    for (int kc = 0; kc < 12; kc++) {
        if (kc < 11) asm volatile("cp.async.wait_group 1;");
        else         asm volatile("cp.async.wait_group 0;");
        __syncthreads();
        uint32_t so = (kc % 3) * (2*STG*2);
        #pragma unroll
        for (int ks = 0; ks < 2; ks++) {
            uint32_t a0[2], a1[2], a2[2], a3[2];
            #pragma unroll
            for (int i = 0; i < 2; i++)
                ldsm4(a0[i], a1[i], a2[i], a3[i], aAddr + so + i*16*80 + ks*32);
            #pragma unroll
            for (int nbp = 0; nbp < 4; nbp++) {
                uint32_t b00, b10, b01, b11;
                ldsm4(b00, b10, b01, b11, bAddr + so + nbp*16*80 + ks*32);
                #pragma unroll
                for (int i = 0; i < 2; i++) {
                    mma_f16(acc[i][2*nbp],   a0[i], a1[i], a2[i], a3[i], b00, b10);
                    mma_f16(acc[i][2*nbp+1], a0[i], a1[i], a2[i], a3[i], b01, b11);
                }
            }
        }
        __syncthreads();
        if (kc + 2 < 12) { ISSUE((kc+2)%3, kc+2); }
    }
    #undef ISSUE

    #pragma unroll
    for (int i = 0; i < 2; i++) {
        int row = m0 + wm*32 + i*16 + g;
        #pragma unroll
        for (int nb = 0; nb < 8; nb++) {
            int col = n0 + wn*64 + nb*8 + 2*c;
            if (OUTH) {
                __half2* Ch = (__half2*)C;
                Ch[((size_t)row*Nn + col) >> 1]     = __floats2half2_rn(acc[i][nb][0], acc[i][nb][1]);
                Ch[((size_t)(row+8)*Nn + col) >> 1] = __floats2half2_rn(acc[i][nb][2], acc[i][nb][3]);
            } else {
                float* Cf = (float*)C;
                *(float2*)(Cf + (size_t)row*Nn + col)     = make_float2(acc[i][nb][0], acc[i][nb][1]);
                *(float2*)(Cf + (size_t)(row+8)*Nn + col) = make_float2(acc[i][nb][2], acc[i][nb][3]);
            }
        }
    }
}

// ---------------- column stats, fp16 input ----------------
__global__ __launch_bounds__(256) void colstats_h(const __half* __restrict__ Y, int Ncol,
                                                  const float* __restrict__ gamma,
                                                  const float* __restrict__ beta,
                                                  float* __restrict__ scOut,
                                                  float* __restrict__ shOut) {
    int lc = threadIdx.x & 31;
    int rg = threadIdx.x >> 5;
    int cp = blockIdx.x * 32 + lc;
    const __half2* Y2 = (const __half2*)Y;
    int stride = Ncol >> 1;
    float sx = 0.f, sx2 = 0.f, sy = 0.f, sy2 = 0.f;
    for (int r = rg; r < MM; r += 8) {
        float2 f = __half22float2(Y2[(size_t)r * stride + cp]);
        sx += f.x; sx2 += f.x*f.x; sy += f.y; sy2 += f.y*f.y;
    }
    __shared__ float sA[8][32], sB[8][32], sC2[8][32], sD[8][32];
    sA[rg][lc] = sx; sB[rg][lc] = sx2; sC2[rg][lc] = sy; sD[rg][lc] = sy2;
    __syncthreads();
    if (rg == 0) {
        #pragma unroll
        for (int gg = 1; gg < 8; gg++) {
            sx += sA[gg][lc]; sx2 += sB[gg][lc]; sy += sC2[gg][lc]; sy2 += sD[gg][lc];
        }
        int c0 = 2*cp, c1 = 2*cp + 1;
        float m0 = sx * (1.0f/MM), m1 = sy * (1.0f/MM);
        float v0 = sx2 * (1.0f/MM) - m0*m0;
        float v1 = sy2 * (1.0f/MM) - m1*m1;
        float s0 = gamma[c0] * rsqrtf(v0 + EPSV);
        float s1 = gamma[c1] * rsqrtf(v1 + EPSV);
        scOut[c0] = s0; shOut[c0] = beta[c0] - m0*s0;
        scOut[c1] = s1; shOut[c1] = beta[c1] - m1*s1;
    }
}

// ---------------- column stats, fp32 input ----------------
__global__ __launch_bounds__(256) void colstats_f(const float* __restrict__ Y, int Ncol,
                                                  const float* __restrict__ gamma,
                                                  const float* __restrict__ beta,
                                                  float* __restrict__ scOut,
                                                  float* __restrict__ shOut) {
    int lc = threadIdx.x & 31;
    int rg = threadIdx.x >> 5;
    int c  = blockIdx.x * 32 + lc;
    float s = 0.f, s2 = 0.f;
    for (int r = rg; r < MM; r += 8) {
        float v = Y[(size_t)r * Ncol + c];
        s += v; s2 += v * v;
    }
    __shared__ float sh[8][32], sh2[8][32];
    sh[rg][lc] = s; sh2[rg][lc] = s2;
    __syncthreads();
    if (rg == 0) {
        #pragma unroll
        for (int gg = 1; gg < 8; gg++) { s += sh[gg][lc]; s2 += sh2[gg][lc]; }
        float mean = s * (1.0f / MM);
        float var  = s2 * (1.0f / MM) - mean * mean;
        float sc   = gamma[c] * rsqrtf(var + EPSV);
        scOut[c] = sc;
        shOut[c] = beta[c] - mean * sc;
    }
}

// ---------------- fused attention: BN folded, raw cp.async K/V, ldmatrix ----------------
// smem halfs: Qh @0 [112][56], Kh @6272 [2][64][56], Vh @13440 [2][64][56], Ph @20608 [112][72]
// fp32 @ float-idx 14336: bias[784], lsum[112], uRow[112], aq/bq/ak/bk/cv/ev [48]x6
// total 62528 bytes
__global__ __launch_bounds__(224, 2) void attn_kernel(const __half* __restrict__ Y,
                                                      const float* __restrict__ biases,
                                                      const float* __restrict__ sc1,
                                                      const float* __restrict__ sh1,
                                                      __half* __restrict__ Ohs) {
    extern __shared__ uint32_t sm[];
    float* smf = (float*)sm;
    __half* smh = (__half*)sm;
    const int QH = 0, KH = 6272, VH = 13440, PH = 20608;
    const int STAGE = 64*56;                 // halfs per K/V stage
    float* biasRow = smf + 14336;            // 784
    float* lsumf   = smf + 15120;            // 112
    float* uRow    = smf + 15232;            // 112
    float* aq = smf + 15344; float* bq = smf + 15392;
    float* ak = smf + 15440; float* bk = smf + 15488;
    float* cv = smf + 15536; float* ev = smf + 15584;

    int t = threadIdx.x;
    int w = t >> 5, L = t & 31;
    int g = L >> 2, c = L & 3;
    int m0l = w * 16;
    int bh = blockIdx.y;
    int b = bh >> 3, h = bh & 7;
    int q0 = blockIdx.x * 112;

    uint32_t base = smem_u32(sm);
    uint32_t kBase = base + KH*2, vBase = base + VH*2;

    // ---- issue raw K/V tile via cp.async (zero ALU conversion) ----
    #define ISSUE_TILE(kt, stage) { \
        int k0i = (kt) * 64; \
        for (int idx = t; idx < 768; idx += 224) { \
            int hv  = idx >= 384; \
            int rem = idx - hv*384; \
            int row = rem / 6, seg = rem - row*6; \
            int n = k0i + row; if (n > NN-1) n = NN-1; \
            const __half* src = Y + (size_t)(b*NN + n)*INNER + (hv ? 768 : 384) + h*HD + seg*8; \
            uint32_t dst = (hv ? vBase : kBase) + (stage)*STAGE*2 + (row*56 + seg*8)*2; \
            asm volatile("cp.async.ca.shared.global [%0], [%1], 16;" :: "r"(dst), "l"(src)); \
        } \
        asm volatile("cp.async.commit_group;"); }

    ISSUE_TILE(0, 0);
    ISSUE_TILE(1, 1);

    // consts
    for (int i = t; i < 288; i += 224) {
        int which = i / 48, d = i - which*48;
        int p = which >> 1;
        float v = (which & 1) ? sh1[p*CC + h*HD + d] : sc1[p*CC + h*HD + d];
        smf[15344 + which*48 + d] = v;   // order: aq,bq,ak,bk,cv,ev
    }
    for (int i = t; i < NN; i += 224) biasRow[i] = biases[h * NN + i] * 1.4426950408889634f;
    if (t < 112) lsumf[t] = 0.f;
    __syncthreads();

    const float scale = 0.14433756729740643f;            // 48^-0.5
    const float cs = scale * 1.4426950408889634f;        // *log2(e)

    // ---- Q load + BN fold: q' = q*aq+bq ; t_i = sum q'*bk ; q'' = q'*ak ----
    {
        int row = t >> 1, ds = (t & 1) * 24;
        const __half2* src = (const __half2*)(Y + (size_t)(b*NN + q0 + row)*INNER + h*HD + ds);
        float tpart = 0.f;
        #pragma unroll
        for (int j = 0; j < 12; j++) {
            int d = ds + 2*j;
            float2 f = __half22float2(src[j]);
            float q0f = fmaf(f.x, aq[d],   bq[d]);
            float q1f = fmaf(f.y, aq[d+1], bq[d+1]);
            tpart = fmaf(q0f, bk[d], tpart);
            tpart = fmaf(q1f, bk[d+1], tpart);
            sm[QH/2 + row*28 + ds/2 + j] = pack2(q0f*ak[d], q1f*ak[d+1]);
        }
        tpart += __shfl_xor_sync(0xffffffffu, tpart, 1);
        if ((t & 1) == 0) uRow[row] = cs * tpart;
    }

    // per-thread query coords for bias-index math
    int qr0 = q0 + m0l + g, qr1 = qr0 + 8;
    int xi0 = qr0 / 28, yi0 = qr0 - xi0 * 28;
    int xi1 = qr1 / 28, yi1 = qr1 - xi1 * 28;

    // ldmatrix lane addresses
    int r8 = L & 7, sel = L >> 3;
    uint32_t qA = base + QH*2 + ((m0l + (L & 15))*56 + (L >> 4)*8)*2;            // + ks*32
    uint32_t pA = base + PH*2 + ((m0l + (L & 15))*72 + (L >> 4)*8)*2;            // + ks*32
    uint32_t kB_rel = (uint32_t)((((sel >> 1)*8 + r8)*56 + (sel & 1)*8)*2);      // + nbp*16*112 + ks*32
    uint32_t vB_rel = (uint32_t)((((sel & 1)*8 + r8)*56)*2 + (sel >> 1)*16);     // + ks*16*112 + nbp*32

    float Oc[6][4] = {};
    float u0 = 0.f, u1 = 0.f;

    for (int kt = 0; kt < 13; kt++) {
        int k0 = kt * 64;
        uint32_t so = (kt & 1) * STAGE*2;
        if (kt < 12) asm volatile("cp.async.wait_group 1;");
        else         asm volatile("cp.async.wait_group 0;");
        __syncthreads();
        if (kt == 0) { u0 = uRow[m0l + g]; u1 = uRow[m0l + 8 + g]; }

        // S = Q'' K_raw^T : m16 x n64, k48
        float Sc[8][4] = {};
        #pragma unroll
        for (int ks = 0; ks < 3; ks++) {
            uint32_t a0, a1, a2, a3;
            ldsm4(a0, a1, a2, a3, qA + ks*32);
            #pragma unroll
            for (int nbp = 0; nbp < 4; nbp++) {
                uint32_t b00, b10, b01, b11;
                ldsm4(b00, b10, b01, b11, kBase + so + nbp*16*112 + ks*32 + kB_rel);
                mma_f16(Sc[2*nbp],   a0, a1, a2, a3, b00, b10);
                mma_f16(Sc[2*nbp+1], a0, a1, a2, a3, b01, b11);
            }
        }

        // P = exp2(cs*S + u_i + bias)
        float rs0 = 0.f, rs1 = 0.f;
        #pragma unroll
        for (int nb = 0; nb < 8; nb++) {
            int col0 = nb*8 + 2*c;
            int kj = k0 + col0;
            float p0 = 0.f, p1 = 0.f, p2 = 0.f, p3 = 0.f;
            if (kj < NN) {
                int xj = kj / 28, yj = kj - xj * 28;
                float b0v = biasRow[abs(xi0 - xj)*28 + abs(yi0 - yj)];
                float b2v = biasRow[abs(xi1 - xj)*28 + abs(yi1 - yj)];
                p0 = fexp2f(fmaf(Sc[nb][0], cs, u0 + b0v));
                p2 = fexp2f(fmaf(Sc[nb][2], cs, u1 + b2v));
            }
            if (kj + 1 < NN) {
                int kj1 = kj + 1;
                int xj = kj1 / 28, yj = kj1 - xj * 28;
                float b1v = biasRow[abs(xi0 - xj)*28 + abs(yi0 - yj)];
                float b3v = biasRow[abs(xi1 - xj)*28 + abs(yi1 - yj)];
                p1 = fexp2f(fmaf(Sc[nb][1], cs, u0 + b1v));
                p3 = fexp2f(fmaf(Sc[nb][3], cs, u1 + b3v));
            }
            rs0 += p0 + p1; rs1 += p2 + p3;
            sm[PH/2 + (m0l + g)*36 + nb*4 + c]     = pack2(p0, p1);
            sm[PH/2 + (m0l + 8 + g)*36 + nb*4 + c] = pack2(p2, p3);
        }
        rs0 += __shfl_xor_sync(0xffffffffu, rs0, 1);
        rs0 += __shfl_xor_sync(0xffffffffu, rs0, 2);
        rs1 += __shfl_xor_sync(0xffffffffu, rs1, 1);
        rs1 += __shfl_xor_sync(0xffffffffu, rs1, 2);
        if (c == 0) {
            lsumf[m0l + g]     += rs0;
            lsumf[m0l + 8 + g] += rs1;
        }
        __syncwarp();

        // O += P V_raw : m16 x d48, k64 — V via ldmatrix.trans (no transpose pass)
        #pragma unroll
        for (int ks = 0; ks < 4; ks++) {
            uint32_t a0, a1, a2, a3;
            ldsm4(a0, a1, a2, a3, pA + ks*32);
            #pragma unroll
            for (int nbp = 0; nbp < 3; nbp++) {
                uint32_t b00, b10, b01, b11;
                ldsm4t(b00, b10, b01, b11, vBase + so + ks*16*112 + nbp*32 + vB_rel);
                mma_f16(Oc[2*nbp],   a0, a1, a2, a3, b00, b10);
                mma_f16(Oc[2*nbp+1], a0, a1, a2, a3, b01, b11);
            }
        }
        __syncthreads();
        if (kt + 2 < 13) { ISSUE_TILE(kt + 2, kt & 1); }
    }
    #undef ISSUE_TILE

    // epilogue: o = cv*(PV/ls) + ev -> hardswish -> fp16
    float inv0 = 1.0f / lsumf[m0l + g];
    float inv1 = 1.0f / lsumf[m0l + 8 + g];
    int n0g = q0 + m0l + g, n1g = n0g + 8;
    __half2* O2 = (__half2*)Ohs;
    #pragma unroll
    for (int nb = 0; nb < 6; nb++) {
        int d = nb*8 + 2*c;
        float o00 = fmaf(Oc[nb][0]*inv0, cv[d],   ev[d]);
        float o01 = fmaf(Oc[nb][1]*inv0, cv[d+1], ev[d+1]);
        float o10 = fmaf(Oc[nb][2]*inv1, cv[d],   ev[d]);
        float o11 = fmaf(Oc[nb][3]*inv1, cv[d+1], ev[d+1]);
        O2[((size_t)(b*NN + n0g)*CC + h*HD + d) >> 1] = __floats2half2_rn(hswish(o00), hswish(o01));
        O2[((size_t)(b*NN + n1g)*CC + h*HD + d) >> 1] = __floats2half2_rn(hswish(o10), hswish(o11));
    }
}

// ---------------- final BN apply ----------------
__global__ __launch_bounds__(256) void apply_bn(const float* __restrict__ Z,
                                                const float* __restrict__ sc,
                                                const float* __restrict__ sh,
                                                float* __restrict__ out) {
    size_t base = ((size_t)blockIdx.x * 256 + threadIdx.x) * 4;
    if (base < (size_t)MM * CC) {
        float4 z = *(const float4*)(Z + base);
        int c = (int)(base % CC);
        float4 o;
        o.x = z.x * sc[c+0] + sh[c+0];
        o.y = z.y * sc[c+1] + sh[c+1];
        o.z = z.z * sc[c+2] + sh[c+2];
        o.w = z.w * sc[c+3] + sh[c+3];
        *(float4*)(out + base) = o;
    }
}

extern "C" void kernel_launch(void* const* d_in, const int* in_sizes, int n_in,
                              void* d_out, int out_size) {
    const float* x      = (const float*)d_in[0];
    const float* Wqkv   = (const float*)d_in[1];
    const float* g1     = (const float*)d_in[2];
    const float* b1     = (const float*)d_in[3];
    const float* Wproj  = (const float*)d_in[4];
    const float* g2     = (const float*)d_in[5];
    const float* b2     = (const float*)d_in[6];
    const float* biases = (const float*)d_in[7];
    float* out = (float*)d_out;

    __half *xh, *wqh, *wph, *yh, *ohsh;
    float *sc1, *sh1, *zp, *sc2, *sh2;
    cudaGetSymbolAddress((void**)&xh,   g_xh);
    cudaGetSymbolAddress((void**)&wqh,  g_wqh);
    cudaGetSymbolAddress((void**)&wph,  g_wph);
    cudaGetSymbolAddress((void**)&yh,   g_yh);
    cudaGetSymbolAddress((void**)&sc1,  g_sc1);
    cudaGetSymbolAddress((void**)&sh1,  g_sh1);
    cudaGetSymbolAddress((void**)&ohsh, g_ohsh);
    cudaGetSymbolAddress((void**)&zp,   g_z);
    cudaGetSymbolAddress((void**)&sc2,  g_sc2);
    cudaGetSymbolAddress((void**)&sh2,  g_sh2);

    cudaFuncSetAttribute(gemm_cp<1>, cudaFuncAttributeMaxDynamicSharedMemorySize, 61440);
    cudaFuncSetAttribute(gemm_cp<0>, cudaFuncAttributeMaxDynamicSharedMemorySize, 61440);
    cudaFuncSetAttribute(attn_kernel, cudaFuncAttributeMaxDynamicSharedMemorySize, 62528);

    f2h<<<(MM*CC/4 + 255)/256, 256>>>(x, xh, MM*CC/4);
    f2h<<<(INNER*CC/4 + 255)/256, 256>>>(Wqkv, wqh, INNER*CC/4);
    f2h<<<(CC*CC/4 + 255)/256, 256>>>(Wproj, wph, CC*CC/4);

    gemm_cp<1><<<dim3(INNER/128, MM/128), 256, 61440>>>(xh, wqh, yh, INNER);
    colstats_h<<<INNER/64, 256>>>(yh, INNER, g1, b1, sc1, sh1);
    attn_kernel<<<dim3(7, BB*HH), 224, 62528>>>(yh, biases, sc1, sh1, ohsh);
    gemm_cp<0><<<dim3(CC/128, MM/128), 256, 61440>>>(ohsh, wph, zp, CC);
    colstats_f<<<CC/32, 256>>>(zp, CC, g2, b2, sc2, sh2);
    apply_bn<<<(MM*CC/4 + 255)/256, 256>>>(zp, sc2, sh2, out);
}

// round 7
// speedup vs baseline: 1.8292x; 1.0243x over previous
#include <cuda_runtime.h>
#include <cuda_fp16.h>
#include <math.h>
#include <stdint.h>

#define BB 16
#define NN 784
#define CC 384
#define HH 8
#define HD 48
#define INNER 1152
#define MM (BB*NN)          // 12544
#define EPSV 1e-5f

// ---------------- scratch ----------------
__device__ __half g_xh[(size_t)MM * CC];
__device__ __half g_wqh[(size_t)INNER * CC];
__device__ __half g_wph[(size_t)CC * CC];
__device__ __half g_yh[(size_t)MM * INNER];     // qkv pre-norm, fp16 (28.9 MB)
__device__ float  g_sc1[INNER];
__device__ float  g_sh1[INNER];
__device__ __half g_ohsh[(size_t)MM * CC];      // hardswish(attn out), fp16
__device__ float  g_z[(size_t)MM * CC];         // proj pre-norm, fp32
__device__ float  g_sc2[CC];
__device__ float  g_sh2[CC];

// ---------------- helpers ----------------
__device__ __forceinline__ uint32_t pack2(float a, float b) {
    __half2 h = __floats2half2_rn(a, b);
    return *reinterpret_cast<uint32_t*>(&h);
}
__device__ __forceinline__ uint32_t smem_u32(const void* p) {
    return (uint32_t)__cvta_generic_to_shared(p);
}
__device__ __forceinline__ void mma_f16(float* c,
        uint32_t a0, uint32_t a1, uint32_t a2, uint32_t a3,
        uint32_t b0, uint32_t b1) {
    asm volatile("mma.sync.aligned.m16n8k16.row.col.f32.f16.f16.f32 "
                 "{%0,%1,%2,%3},{%4,%5,%6,%7},{%8,%9},{%0,%1,%2,%3};"
                 : "+f"(c[0]), "+f"(c[1]), "+f"(c[2]), "+f"(c[3])
                 : "r"(a0), "r"(a1), "r"(a2), "r"(a3), "r"(b0), "r"(b1));
}
__device__ __forceinline__ void ldsm4(uint32_t& r0, uint32_t& r1, uint32_t& r2, uint32_t& r3, uint32_t a) {
    asm volatile("ldmatrix.sync.aligned.m8n8.x4.shared.b16 {%0,%1,%2,%3}, [%4];"
                 : "=r"(r0),"=r"(r1),"=r"(r2),"=r"(r3) : "r"(a));
}
__device__ __forceinline__ void ldsm4t(uint32_t& r0, uint32_t& r1, uint32_t& r2, uint32_t& r3, uint32_t a) {
    asm volatile("ldmatrix.sync.aligned.m8n8.x4.trans.shared.b16 {%0,%1,%2,%3}, [%4];"
                 : "=r"(r0),"=r"(r1),"=r"(r2),"=r"(r3) : "r"(a));
}
__device__ __forceinline__ float fexp2f(float y) {
    float r = y + 12582912.0f;
    float i = r - 12582912.0f;
    float f = y - i;
    int   e = __float_as_int(r) << 23;
    float p = 1.5403530393e-4f;
    p = fmaf(p, f, 1.3333558146e-3f);
    p = fmaf(p, f, 9.6181291076e-3f);
    p = fmaf(p, f, 5.5504108664e-2f);
    p = fmaf(p, f, 2.4022650696e-1f);
    p = fmaf(p, f, 6.9314718056e-1f);
    p = fmaf(p, f, 1.0f);
    return __int_as_float(__float_as_int(p) + e);
}
__device__ __forceinline__ float hswish(float v) {
    return v * fminf(fmaxf(v + 3.f, 0.f), 6.f) * (1.0f/6.0f);
}

// ---------------- fp32 -> fp16 convert ----------------
__global__ __launch_bounds__(256) void f2h(const float* __restrict__ in,
                                           __half* __restrict__ out, int n4) {
    int i = blockIdx.x * 256 + threadIdx.x;
    if (i < n4) {
        float4 v = ((const float4*)in)[i];
        __half2* o = (__half2*)out;
        o[2*i]   = __floats2half2_rn(v.x, v.y);
        o[2*i+1] = __floats2half2_rn(v.z, v.w);
    }
}

// ---------------- cp.async pipelined fp16 GEMM NT (K=384), ldmatrix frags ----------------
template<int OUTH>
__global__ __launch_bounds__(256) void gemm_cp(const __half* __restrict__ A,
                                               const __half* __restrict__ Bw,
                                               void* __restrict__ C, int Nn) {
    extern __shared__ __half hs[];          // [3][2][128*40]
    const int STG = 128*40;
    int t = threadIdx.x;
    int w = t >> 5, L = t & 31;
    int g = L >> 2, c = L & 3;
    int wm = w & 3, wn = w >> 2;
    int m0 = blockIdx.y * 128, n0 = blockIdx.x * 128;

    int id0 = t, id1 = t + 256;
    int ra0 = id0 >> 2, oa0 = (id0 & 3) * 8;
    int ra1 = id1 >> 2, oa1 = (id1 & 3) * 8;
    const __half* Ap0 = A  + (size_t)(m0 + ra0) * 384 + oa0;
    const __half* Ap1 = A  + (size_t)(m0 + ra1) * 384 + oa1;
    const __half* Bp0 = Bw + (size_t)(n0 + ra0) * 384 + oa0;
    const __half* Bp1 = Bw + (size_t)(n0 + ra1) * 384 + oa1;

    uint32_t base = smem_u32(hs);
    uint32_t dA0 = base + (ra0*40 + oa0)*2;
    uint32_t dA1 = base + (ra1*40 + oa1)*2;
    uint32_t dB0 = base + (STG + ra0*40 + oa0)*2;
    uint32_t dB1 = base + (STG + ra1*40 + oa1)*2;

    int r8 = L & 7, sel = L >> 3;
    uint32_t aAddr = base + ((wm*32 + (L & 15))*40 + (L >> 4)*8)*2;
    uint32_t bAddr = base + STG*2 + ((wn*64 + (sel>>1)*8 + r8)*40 + (sel&1)*8)*2;

    #define ISSUE(st, kc) { \
        int ko = (kc) * 32; uint32_t so = (st) * (2*STG*2); \
        asm volatile("cp.async.ca.shared.global [%0], [%1], 16;" :: "r"(dA0+so), "l"(Ap0+ko)); \
        asm volatile("cp.async.ca.shared.global [%0], [%1], 16;" :: "r"(dA1+so), "l"(Ap1+ko)); \
        asm volatile("cp.async.ca.shared.global [%0], [%1], 16;" :: "r"(dB0+so), "l"(Bp0+ko)); \
        asm volatile("cp.async.ca.shared.global [%0], [%1], 16;" :: "r"(dB1+so), "l"(Bp1+ko)); \
        asm volatile("cp.async.commit_group;"); }

    float acc[2][8][4] = {};
    ISSUE(0, 0); ISSUE(1, 1);

    for (int kc = 0; kc < 12; kc++) {
        if (kc < 11) asm volatile("cp.async.wait_group 1;");
        else         asm volatile("cp.async.wait_group 0;");
        __syncthreads();
        uint32_t so = (kc % 3) * (2*STG*2);
        #pragma unroll
        for (int ks = 0; ks < 2; ks++) {
            uint32_t a0[2], a1[2], a2[2], a3[2];
            #pragma unroll
            for (int i = 0; i < 2; i++)
                ldsm4(a0[i], a1[i], a2[i], a3[i], aAddr + so + i*16*80 + ks*32);
            #pragma unroll
            for (int nbp = 0; nbp < 4; nbp++) {
                uint32_t b00, b10, b01, b11;
                ldsm4(b00, b10, b01, b11, bAddr + so + nbp*16*80 + ks*32);
                #pragma unroll
                for (int i = 0; i < 2; i++) {
                    mma_f16(acc[i][2*nbp],   a0[i], a1[i], a2[i], a3[i], b00, b10);
                    mma_f16(acc[i][2*nbp+1], a0[i], a1[i], a2[i], a3[i], b01, b11);
                }
            }
        }
        __syncthreads();
        if (kc + 2 < 12) { ISSUE((kc+2)%3, kc+2); }
    }
    #undef ISSUE

    #pragma unroll
    for (int i = 0; i < 2; i++) {
        int row = m0 + wm*32 + i*16 + g;
        #pragma unroll
        for (int nb = 0; nb < 8; nb++) {
            int col = n0 + wn*64 + nb*8 + 2*c;
            if (OUTH) {
                __half2* Ch = (__half2*)C;
                Ch[((size_t)row*Nn + col) >> 1]     = __floats2half2_rn(acc[i][nb][0], acc[i][nb][1]);
                Ch[((size_t)(row+8)*Nn + col) >> 1] = __floats2half2_rn(acc[i][nb][2], acc[i][nb][3]);
            } else {
                float* Cf = (float*)C;
                *(float2*)(Cf + (size_t)row*Nn + col)     = make_float2(acc[i][nb][0], acc[i][nb][1]);
                *(float2*)(Cf + (size_t)(row+8)*Nn + col) = make_float2(acc[i][nb][2], acc[i][nb][3]);
            }
        }
    }
}

// ---------------- column stats, fp16 input ----------------
__global__ __launch_bounds__(256) void colstats_h(const __half* __restrict__ Y, int Ncol,
                                                  const float* __restrict__ gamma,
                                                  const float* __restrict__ beta,
                                                  float* __restrict__ scOut,
                                                  float* __restrict__ shOut) {
    int lc = threadIdx.x & 31;
    int rg = threadIdx.x >> 5;
    int cp = blockIdx.x * 32 + lc;
    const __half2* Y2 = (const __half2*)Y;
    int stride = Ncol >> 1;
    float sx = 0.f, sx2 = 0.f, sy = 0.f, sy2 = 0.f;
    for (int r = rg; r < MM; r += 8) {
        float2 f = __half22float2(Y2[(size_t)r * stride + cp]);
        sx += f.x; sx2 += f.x*f.x; sy += f.y; sy2 += f.y*f.y;
    }
    __shared__ float sA[8][32], sB[8][32], sC2[8][32], sD[8][32];
    sA[rg][lc] = sx; sB[rg][lc] = sx2; sC2[rg][lc] = sy; sD[rg][lc] = sy2;
    __syncthreads();
    if (rg == 0) {
        #pragma unroll
        for (int gg = 1; gg < 8; gg++) {
            sx += sA[gg][lc]; sx2 += sB[gg][lc]; sy += sC2[gg][lc]; sy2 += sD[gg][lc];
        }
        int c0 = 2*cp, c1 = 2*cp + 1;
        float m0 = sx * (1.0f/MM), m1 = sy * (1.0f/MM);
        float v0 = sx2 * (1.0f/MM) - m0*m0;
        float v1 = sy2 * (1.0f/MM) - m1*m1;
        float s0 = gamma[c0] * rsqrtf(v0 + EPSV);
        float s1 = gamma[c1] * rsqrtf(v1 + EPSV);
        scOut[c0] = s0; shOut[c0] = beta[c0] - m0*s0;
        scOut[c1] = s1; shOut[c1] = beta[c1] - m1*s1;
    }
}

// ---------------- column stats, fp32 input ----------------
__global__ __launch_bounds__(256) void colstats_f(const float* __restrict__ Y, int Ncol,
                                                  const float* __restrict__ gamma,
                                                  const float* __restrict__ beta,
                                                  float* __restrict__ scOut,
                                                  float* __restrict__ shOut) {
    int lc = threadIdx.x & 31;
    int rg = threadIdx.x >> 5;
    int c  = blockIdx.x * 32 + lc;
    float s = 0.f, s2 = 0.f;
    for (int r = rg; r < MM; r += 8) {
        float v = Y[(size_t)r * Ncol + c];
        s += v; s2 += v * v;
    }
    __shared__ float sh[8][32], sh2[8][32];
    sh[rg][lc] = s; sh2[rg][lc] = s2;
    __syncthreads();
    if (rg == 0) {
        #pragma unroll
        for (int gg = 1; gg < 8; gg++) { s += sh[gg][lc]; s2 += sh2[gg][lc]; }
        float mean = s * (1.0f / MM);
        float var  = s2 * (1.0f / MM) - mean * mean;
        float sc   = gamma[c] * rsqrtf(var + EPSV);
        scOut[c] = sc;
        shOut[c] = beta[c] - mean * sc;
    }
}

// ---------------- fused attention: P in registers, hoisted Q frags ----------------
// smem halfs: Qh @0 [112][56] (6272), Kh @6272 [2][64][56] (7168), Vh @13440 [2][64][56] (7168)
// floats from idx 10304: bias[784], uRow[112], consts aq/bq/ak/bk/cv/ev [48]x6 (288)
// total = 45952 bytes
__global__ __launch_bounds__(224, 2) void attn_kernel(const __half* __restrict__ Y,
                                                      const float* __restrict__ biases,
                                                      const float* __restrict__ sc1,
                                                      const float* __restrict__ sh1,
                                                      __half* __restrict__ Ohs) {
    extern __shared__ uint32_t sm[];
    float* smf = (float*)sm;
    const int QH = 0, KH = 6272, VH = 13440;
    const int STAGE = 64*56;                 // halfs per K/V stage
    float* biasRow = smf + 10304;            // 784
    float* uRow    = smf + 11088;            // 112
    float* aq = smf + 11200; float* bq = smf + 11248;
    float* ak = smf + 11296; float* bk = smf + 11344;
    float* cv = smf + 11392; float* ev = smf + 11440;

    int t = threadIdx.x;
    int w = t >> 5, L = t & 31;
    int g = L >> 2, c = L & 3;
    int m0l = w * 16;
    int bh = blockIdx.y;
    int b = bh >> 3, h = bh & 7;
    int q0 = blockIdx.x * 112;

    uint32_t base = smem_u32(sm);
    uint32_t kBase = base + KH*2, vBase = base + VH*2;

    #define ISSUE_TILE(kt, stage) { \
        int k0i = (kt) * 64; \
        for (int idx = t; idx < 768; idx += 224) { \
            int hv  = idx >= 384; \
            int rem = idx - hv*384; \
            int row = rem / 6, seg = rem - row*6; \
            int n = k0i + row; if (n > NN-1) n = NN-1; \
            const __half* src = Y + (size_t)(b*NN + n)*INNER + (hv ? 768 : 384) + h*HD + seg*8; \
            uint32_t dst = (hv ? vBase : kBase) + (stage)*STAGE*2 + (row*56 + seg*8)*2; \
            asm volatile("cp.async.ca.shared.global [%0], [%1], 16;" :: "r"(dst), "l"(src)); \
        } \
        asm volatile("cp.async.commit_group;"); }

    ISSUE_TILE(0, 0);
    ISSUE_TILE(1, 1);

    // consts (order: aq,bq,ak,bk,cv,ev)
    for (int i = t; i < 288; i += 224) {
        int which = i / 48, d = i - which*48;
        int p = which >> 1;
        float v = (which & 1) ? sh1[p*CC + h*HD + d] : sc1[p*CC + h*HD + d];
        smf[11200 + which*48 + d] = v;
    }
    for (int i = t; i < NN; i += 224) biasRow[i] = biases[h * NN + i] * 1.4426950408889634f;
    __syncthreads();   // consts ready for Q fold

    const float scale = 0.14433756729740643f;            // 48^-0.5
    const float cs = scale * 1.4426950408889634f;        // *log2(e)

    // ---- Q load + BN fold ----
    {
        int row = t >> 1, ds = (t & 1) * 24;
        const __half2* src = (const __half2*)(Y + (size_t)(b*NN + q0 + row)*INNER + h*HD + ds);
        float tpart = 0.f;
        #pragma unroll
        for (int j = 0; j < 12; j++) {
            int d = ds + 2*j;
            float2 f = __half22float2(src[j]);
            float q0f = fmaf(f.x, aq[d],   bq[d]);
            float q1f = fmaf(f.y, aq[d+1], bq[d+1]);
            tpart = fmaf(q0f, bk[d], tpart);
            tpart = fmaf(q1f, bk[d+1], tpart);
            sm[QH/2 + row*28 + ds/2 + j] = pack2(q0f*ak[d], q1f*ak[d+1]);
        }
        tpart += __shfl_xor_sync(0xffffffffu, tpart, 1);
        if ((t & 1) == 0) uRow[row] = cs * tpart;
    }
    __syncthreads();   // Qh + uRow visible

    // hoisted loop-invariant Q fragments
    uint32_t qA = base + QH*2 + ((m0l + (L & 15))*56 + (L >> 4)*8)*2;
    uint32_t qa0[3], qa1[3], qa2[3], qa3[3];
    #pragma unroll
    for (int ks = 0; ks < 3; ks++)
        ldsm4(qa0[ks], qa1[ks], qa2[ks], qa3[ks], qA + ks*32);
    float u0 = uRow[m0l + g];
    float u1 = uRow[m0l + 8 + g];

    // per-thread query coords for bias-index math
    int qr0 = q0 + m0l + g, qr1 = qr0 + 8;
    int xi0 = qr0 / 28, yi0 = qr0 - xi0 * 28;
    int xi1 = qr1 / 28, yi1 = qr1 - xi1 * 28;

    int r8 = L & 7, sel = L >> 3;
    uint32_t kB_rel = (uint32_t)((((sel >> 1)*8 + r8)*56 + (sel & 1)*8)*2);
    uint32_t vB_rel = (uint32_t)((((sel & 1)*8 + r8)*56)*2 + (sel >> 1)*16);

    float Oc[6][4] = {};
    float lsum0 = 0.f, lsum1 = 0.f;

    for (int kt = 0; kt < 13; kt++) {
        int k0 = kt * 64;
        uint32_t so = (kt & 1) * STAGE*2;
        if (kt < 12) asm volatile("cp.async.wait_group 1;");
        else         asm volatile("cp.async.wait_group 0;");
        __syncthreads();

        // S = Q'' K_raw^T : m16 x n64, k48
        float Sc[8][4] = {};
        #pragma unroll
        for (int ks = 0; ks < 3; ks++) {
            #pragma unroll
            for (int nbp = 0; nbp < 4; nbp++) {
                uint32_t b00, b10, b01, b11;
                ldsm4(b00, b10, b01, b11, kBase + so + nbp*16*112 + ks*32 + kB_rel);
                mma_f16(Sc[2*nbp],   qa0[ks], qa1[ks], qa2[ks], qa3[ks], b00, b10);
                mma_f16(Sc[2*nbp+1], qa0[ks], qa1[ks], qa2[ks], qa3[ks], b01, b11);
            }
        }

        // P = exp2(cs*S + u_i + bias), kept in registers
        float Pv[8][4];
        #pragma unroll
        for (int nb = 0; nb < 8; nb++) {
            int col0 = nb*8 + 2*c;
            int kj = k0 + col0;
            float p0 = 0.f, p1 = 0.f, p2 = 0.f, p3 = 0.f;
            if (kj < NN) {
                int xj = kj / 28, yj = kj - xj * 28;
                float b0v = biasRow[abs(xi0 - xj)*28 + abs(yi0 - yj)];
                float b2v = biasRow[abs(xi1 - xj)*28 + abs(yi1 - yj)];
                p0 = fexp2f(fmaf(Sc[nb][0], cs, u0 + b0v));
                p2 = fexp2f(fmaf(Sc[nb][2], cs, u1 + b2v));
            }
            if (kj + 1 < NN) {
                int kj1 = kj + 1;
                int xj = kj1 / 28, yj = kj1 - xj * 28;
                float b1v = biasRow[abs(xi0 - xj)*28 + abs(yi0 - yj)];
                float b3v = biasRow[abs(xi1 - xj)*28 + abs(yi1 - yj)];
                p1 = fexp2f(fmaf(Sc[nb][1], cs, u0 + b1v));
                p3 = fexp2f(fmaf(Sc[nb][3], cs, u1 + b3v));
            }
            Pv[nb][0] = p0; Pv[nb][1] = p1; Pv[nb][2] = p2; Pv[nb][3] = p3;
            lsum0 += p0 + p1; lsum1 += p2 + p3;
        }

        // O += P V_raw : P fed directly from registers (acc layout == A-frag layout)
        #pragma unroll
        for (int ks = 0; ks < 4; ks++) {
            uint32_t a0 = pack2(Pv[2*ks][0],   Pv[2*ks][1]);
            uint32_t a1 = pack2(Pv[2*ks][2],   Pv[2*ks][3]);
            uint32_t a2 = pack2(Pv[2*ks+1][0], Pv[2*ks+1][1]);
            uint32_t a3 = pack2(Pv[2*ks+1][2], Pv[2*ks+1][3]);
            #pragma unroll
            for (int nbp = 0; nbp < 3; nbp++) {
                uint32_t b00, b10, b01, b11;
                ldsm4t(b00, b10, b01, b11, vBase + so + ks*16*112 + nbp*32 + vB_rel);
                mma_f16(Oc[2*nbp],   a0, a1, a2, a3, b00, b10);
                mma_f16(Oc[2*nbp+1], a0, a1, a2, a3, b01, b11);
            }
        }
        __syncthreads();
        if (kt + 2 < 13) { ISSUE_TILE(kt + 2, kt & 1); }
    }
    #undef ISSUE_TILE

    // row-sum reduce across the 4 c-lanes (same g)
    lsum0 += __shfl_xor_sync(0xffffffffu, lsum0, 1);
    lsum0 += __shfl_xor_sync(0xffffffffu, lsum0, 2);
    lsum1 += __shfl_xor_sync(0xffffffffu, lsum1, 1);
    lsum1 += __shfl_xor_sync(0xffffffffu, lsum1, 2);

    // epilogue: o = cv*(PV/ls) + ev -> hardswish -> fp16
    float inv0 = 1.0f / lsum0;
    float inv1 = 1.0f / lsum1;
    int n0g = q0 + m0l + g, n1g = n0g + 8;
    __half2* O2 = (__half2*)Ohs;
    #pragma unroll
    for (int nb = 0; nb < 6; nb++) {
        int d = nb*8 + 2*c;
        float o00 = fmaf(Oc[nb][0]*inv0, cv[d],   ev[d]);
        float o01 = fmaf(Oc[nb][1]*inv0, cv[d+1], ev[d+1]);
        float o10 = fmaf(Oc[nb][2]*inv1, cv[d],   ev[d]);
        float o11 = fmaf(Oc[nb][3]*inv1, cv[d+1], ev[d+1]);
        O2[((size_t)(b*NN + n0g)*CC + h*HD + d) >> 1] = __floats2half2_rn(hswish(o00), hswish(o01));
        O2[((size_t)(b*NN + n1g)*CC + h*HD + d) >> 1] = __floats2half2_rn(hswish(o10), hswish(o11));
    }
}

// ---------------- final BN apply ----------------
__global__ __launch_bounds__(256) void apply_bn(const float* __restrict__ Z,
                                                const float* __restrict__ sc,
                                                const float* __restrict__ sh,
                                                float* __restrict__ out) {
    size_t base = ((size_t)blockIdx.x * 256 + threadIdx.x) * 4;
    if (base < (size_t)MM * CC) {
        float4 z = *(const float4*)(Z + base);
        int c = (int)(base % CC);
        float4 o;
        o.x = z.x * sc[c+0] + sh[c+0];
        o.y = z.y * sc[c+1] + sh[c+1];
        o.z = z.z * sc[c+2] + sh[c+2];
        o.w = z.w * sc[c+3] + sh[c+3];
        *(float4*)(out + base) = o;
    }
}

extern "C" void kernel_launch(void* const* d_in, const int* in_sizes, int n_in,
                              void* d_out, int out_size) {
    const float* x      = (const float*)d_in[0];
    const float* Wqkv   = (const float*)d_in[1];
    const float* g1     = (const float*)d_in[2];
    const float* b1     = (const float*)d_in[3];
    const float* Wproj  = (const float*)d_in[4];
    const float* g2     = (const float*)d_in[5];
    const float* b2     = (const float*)d_in[6];
    const float* biases = (const float*)d_in[7];
    float* out = (float*)d_out;

    __half *xh, *wqh, *wph, *yh, *ohsh;
    float *sc1, *sh1, *zp, *sc2, *sh2;
    cudaGetSymbolAddress((void**)&xh,   g_xh);
    cudaGetSymbolAddress((void**)&wqh,  g_wqh);
    cudaGetSymbolAddress((void**)&wph,  g_wph);
    cudaGetSymbolAddress((void**)&yh,   g_yh);
    cudaGetSymbolAddress((void**)&sc1,  g_sc1);
    cudaGetSymbolAddress((void**)&sh1,  g_sh1);
    cudaGetSymbolAddress((void**)&ohsh, g_ohsh);
    cudaGetSymbolAddress((void**)&zp,   g_z);
    cudaGetSymbolAddress((void**)&sc2,  g_sc2);
    cudaGetSymbolAddress((void**)&sh2,  g_sh2);

    cudaFuncSetAttribute(gemm_cp<1>, cudaFuncAttributeMaxDynamicSharedMemorySize, 61440);
    cudaFuncSetAttribute(gemm_cp<0>, cudaFuncAttributeMaxDynamicSharedMemorySize, 61440);
    cudaFuncSetAttribute(attn_kernel, cudaFuncAttributeMaxDynamicSharedMemorySize, 45952);

    f2h<<<(MM*CC/4 + 255)/256, 256>>>(x, xh, MM*CC/4);
    f2h<<<(INNER*CC/4 + 255)/256, 256>>>(Wqkv, wqh, INNER*CC/4);
    f2h<<<(CC*CC/4 + 255)/256, 256>>>(Wproj, wph, CC*CC/4);

    gemm_cp<1><<<dim3(INNER/128, MM/128), 256, 61440>>>(xh, wqh, yh, INNER);
    colstats_h<<<INNER/64, 256>>>(yh, INNER, g1, b1, sc1, sh1);
    attn_kernel<<<dim3(7, BB*HH), 224, 45952>>>(yh, biases, sc1, sh1, ohsh);
    gemm_cp<0><<<dim3(CC/128, MM/128), 256, 61440>>>(ohsh, wph, zp, CC);
    colstats_f<<<CC/32, 256>>>(zp, CC, g2, b2, sc2, sh2);
    apply_bn<<<(MM*CC/4 + 255)/256, 256>>>(zp, sc2, sh2, out);
}

// round 9
// speedup vs baseline: 1.9926x; 1.0893x over previous
#include <cuda_runtime.h>
#include <cuda_fp16.h>
#include <math.h>
#include <stdint.h>

#define BB 16
#define NN 784
#define CC 384
#define HH 8
#define HD 48
#define INNER 1152
#define MM (BB*NN)          // 12544
#define EPSV 1e-5f

// ---------------- scratch ----------------
__device__ __half g_xh[(size_t)MM * CC];
__device__ __half g_wqh[(size_t)INNER * CC];
__device__ __half g_wph[(size_t)CC * CC];
__device__ __half g_yh[(size_t)MM * INNER];     // qkv pre-norm, fp16 (28.9 MB)
__device__ float  g_sc1[INNER];
__device__ float  g_sh1[INNER];
__device__ __half g_ohsh[(size_t)MM * CC];      // hardswish(attn out), fp16
__device__ float  g_z[(size_t)MM * CC];         // proj pre-norm, fp32
__device__ float  g_sc2[CC];
__device__ float  g_sh2[CC];

// ---------------- helpers ----------------
__device__ __forceinline__ uint32_t pack2(float a, float b) {
    __half2 h = __floats2half2_rn(a, b);
    return *reinterpret_cast<uint32_t*>(&h);
}
__device__ __forceinline__ uint32_t smem_u32(const void* p) {
    return (uint32_t)__cvta_generic_to_shared(p);
}
__device__ __forceinline__ float ex2(float x) {        // MUFU.EX2, one instruction
    float r;
    asm("ex2.approx.f32 %0, %1;" : "=f"(r) : "f"(x));
    return r;
}
__device__ __forceinline__ void mma_f16(float* c,
        uint32_t a0, uint32_t a1, uint32_t a2, uint32_t a3,
        uint32_t b0, uint32_t b1) {
    asm volatile("mma.sync.aligned.m16n8k16.row.col.f32.f16.f16.f32 "
                 "{%0,%1,%2,%3},{%4,%5,%6,%7},{%8,%9},{%0,%1,%2,%3};"
                 : "+f"(c[0]), "+f"(c[1]), "+f"(c[2]), "+f"(c[3])
                 : "r"(a0), "r"(a1), "r"(a2), "r"(a3), "r"(b0), "r"(b1));
}
__device__ __forceinline__ void ldsm4(uint32_t& r0, uint32_t& r1, uint32_t& r2, uint32_t& r3, uint32_t a) {
    asm volatile("ldmatrix.sync.aligned.m8n8.x4.shared.b16 {%0,%1,%2,%3}, [%4];"
                 : "=r"(r0),"=r"(r1),"=r"(r2),"=r"(r3) : "r"(a));
}
__device__ __forceinline__ void ldsm4t(uint32_t& r0, uint32_t& r1, uint32_t& r2, uint32_t& r3, uint32_t a) {
    asm volatile("ldmatrix.sync.aligned.m8n8.x4.trans.shared.b16 {%0,%1,%2,%3}, [%4];"
                 : "=r"(r0),"=r"(r1),"=r"(r2),"=r"(r3) : "r"(a));
}
__device__ __forceinline__ float hswish(float v) {
    return v * fminf(fmaxf(v + 3.f, 0.f), 6.f) * (1.0f/6.0f);
}

// ---------------- fp32 -> fp16 convert ----------------
__global__ __launch_bounds__(256) void f2h(const float* __restrict__ in,
                                           __half* __restrict__ out, int n4) {
    int i = blockIdx.x * 256 + threadIdx.x;
    if (i < n4) {
        float4 v = ((const float4*)in)[i];
        __half2* o = (__half2*)out;
        o[2*i]   = __floats2half2_rn(v.x, v.y);
        o[2*i+1] = __floats2half2_rn(v.z, v.w);
    }
}

// ---------------- cp.async pipelined fp16 GEMM NT (K=384), ldmatrix frags ----------------
// 3-stage; single barrier per k-chunk.
template<int OUTH>
__global__ __launch_bounds__(256) void gemm_cp(const __half* __restrict__ A,
                                               const __half* __restrict__ Bw,
                                               void* __restrict__ C, int Nn) {
    extern __shared__ __half hs[];          // [3][2][128*40]
    const int STG = 128*40;
    int t = threadIdx.x;
    int w = t >> 5, L = t & 31;
    int g = L >> 2, c = L & 3;
    int wm = w & 3, wn = w >> 2;
    int m0 = blockIdx.y * 128, n0 = blockIdx.x * 128;

    int id0 = t, id1 = t + 256;
    int ra0 = id0 >> 2, oa0 = (id0 & 3) * 8;
    int ra1 = id1 >> 2, oa1 = (id1 & 3) * 8;
    const __half* Ap0 = A  + (size_t)(m0 + ra0) * 384 + oa0;
    const __half* Ap1 = A  + (size_t)(m0 + ra1) * 384 + oa1;
    const __half* Bp0 = Bw + (size_t)(n0 + ra0) * 384 + oa0;
    const __half* Bp1 = Bw + (size_t)(n0 + ra1) * 384 + oa1;

    uint32_t base = smem_u32(hs);
    uint32_t dA0 = base + (ra0*40 + oa0)*2;
    uint32_t dA1 = base + (ra1*40 + oa1)*2;
    uint32_t dB0 = base + (STG + ra0*40 + oa0)*2;
    uint32_t dB1 = base + (STG + ra1*40 + oa1)*2;

    int r8 = L & 7, sel = L >> 3;
    uint32_t aAddr = base + ((wm*32 + (L & 15))*40 + (L >> 4)*8)*2;
    uint32_t bAddr = base + STG*2 + ((wn*64 + (sel>>1)*8 + r8)*40 + (sel&1)*8)*2;

    #define ISSUE(st, kc) { \
        int ko = (kc) * 32; uint32_t so = (st) * (2*STG*2); \
        asm volatile("cp.async.ca.shared.global [%0], [%1], 16;" :: "r"(dA0+so), "l"(Ap0+ko)); \
        asm volatile("cp.async.ca.shared.global [%0], [%1], 16;" :: "r"(dA1+so), "l"(Ap1+ko)); \
        asm volatile("cp.async.ca.shared.global [%0], [%1], 16;" :: "r"(dB0+so), "l"(Bp0+ko)); \
        asm volatile("cp.async.ca.shared.global [%0], [%1], 16;" :: "r"(dB1+so), "l"(Bp1+ko)); \
        asm volatile("cp.async.commit_group;"); }

    float acc[2][8][4] = {};
    ISSUE(0, 0); ISSUE(1, 1);

    for (int kc = 0; kc < 12; kc++) {
        if (kc < 11) asm volatile("cp.async.wait_group 1;");
        else         asm volatile("cp.async.wait_group 0;");
        __syncthreads();
        if (kc + 2 < 12) { ISSUE((kc+2)%3, kc+2); }
        uint32_t so = (kc % 3) * (2*STG*2);
        #pragma unroll
        for (int ks = 0; ks < 2; ks++) {
            uint32_t a0[2], a1[2], a2[2], a3[2];
            #pragma unroll
            for (int i = 0; i < 2; i++)
                ldsm4(a0[i], a1[i], a2[i], a3[i], aAddr + so + i*16*80 + ks*32);
            #pragma unroll
            for (int nbp = 0; nbp < 4; nbp++) {
                uint32_t b00, b10, b01, b11;
                ldsm4(b00, b10, b01, b11, bAddr + so + nbp*16*80 + ks*32);
                #pragma unroll
                for (int i = 0; i < 2; i++) {
                    mma_f16(acc[i][2*nbp],   a0[i], a1[i], a2[i], a3[i], b00, b10);
                    mma_f16(acc[i][2*nbp+1], a0[i], a1[i], a2[i], a3[i], b01, b11);
                }
            }
        }
    }
    #undef ISSUE

    #pragma unroll
    for (int i = 0; i < 2; i++) {
        int row = m0 + wm*32 + i*16 + g;
        #pragma unroll
        for (int nb = 0; nb < 8; nb++) {
            int col = n0 + wn*64 + nb*8 + 2*c;
            if (OUTH) {
                __half2* Ch = (__half2*)C;
                Ch[((size_t)row*Nn + col) >> 1]     = __floats2half2_rn(acc[i][nb][0], acc[i][nb][1]);
                Ch[((size_t)(row+8)*Nn + col) >> 1] = __floats2half2_rn(acc[i][nb][2], acc[i][nb][3]);
            } else {
                float* Cf = (float*)C;
                *(float2*)(Cf + (size_t)row*Nn + col)     = make_float2(acc[i][nb][0], acc[i][nb][1]);
                *(float2*)(Cf + (size_t)(row+8)*Nn + col) = make_float2(acc[i][nb][2], acc[i][nb][3]);
            }
        }
    }
}

// ---------------- column stats, fp16 input ----------------
__global__ __launch_bounds__(256) void colstats_h(const __half* __restrict__ Y, int Ncol,
                                                  const float* __restrict__ gamma,
                                                  const float* __restrict__ beta,
                                                  float* __restrict__ scOut,
                                                  float* __restrict__ shOut) {
    int lc = threadIdx.x & 31;
    int rg = threadIdx.x >> 5;
    int cp = blockIdx.x * 32 + lc;
    const __half2* Y2 = (const __half2*)Y;
    int stride = Ncol >> 1;
    float sx = 0.f, sx2 = 0.f, sy = 0.f, sy2 = 0.f;
    for (int r = rg; r < MM; r += 8) {
        float2 f = __half22float2(Y2[(size_t)r * stride + cp]);
        sx += f.x; sx2 += f.x*f.x; sy += f.y; sy2 += f.y*f.y;
    }
    __shared__ float sA[8][32], sB[8][32], sC2[8][32], sD[8][32];
    sA[rg][lc] = sx; sB[rg][lc] = sx2; sC2[rg][lc] = sy; sD[rg][lc] = sy2;
    __syncthreads();
    if (rg == 0) {
        #pragma unroll
        for (int gg = 1; gg < 8; gg++) {
            sx += sA[gg][lc]; sx2 += sB[gg][lc]; sy += sC2[gg][lc]; sy2 += sD[gg][lc];
        }
        int c0 = 2*cp, c1 = 2*cp + 1;
        float m0 = sx * (1.0f/MM), m1 = sy * (1.0f/MM);
        float v0 = sx2 * (1.0f/MM) - m0*m0;
        float v1 = sy2 * (1.0f/MM) - m1*m1;
        float s0 = gamma[c0] * rsqrtf(v0 + EPSV);
        float s1 = gamma[c1] * rsqrtf(v1 + EPSV);
        scOut[c0] = s0; shOut[c0] = beta[c0] - m0*s0;
        scOut[c1] = s1; shOut[c1] = beta[c1] - m1*s1;
    }
}

// ---------------- column stats, fp32 input ----------------
__global__ __launch_bounds__(256) void colstats_f(const float* __restrict__ Y, int Ncol,
                                                  const float* __restrict__ gamma,
                                                  const float* __restrict__ beta,
                                                  float* __restrict__ scOut,
                                                  float* __restrict__ shOut) {
    int lc = threadIdx.x & 31;
    int rg = threadIdx.x >> 5;
    int c  = blockIdx.x * 32 + lc;
    float s = 0.f, s2 = 0.f;
    for (int r = rg; r < MM; r += 8) {
        float v = Y[(size_t)r * Ncol + c];
        s += v; s2 += v * v;
    }
    __shared__ float sh[8][32], sh2[8][32];
    sh[rg][lc] = s; sh2[rg][lc] = s2;
    __syncthreads();
    if (rg == 0) {
        #pragma unroll
        for (int gg = 1; gg < 8; gg++) { s += sh[gg][lc]; s2 += sh2[gg][lc]; }
        float mean = s * (1.0f / MM);
        float var  = s2 * (1.0f / MM) - mean * mean;
        float sc   = gamma[c] * rsqrtf(var + EPSV);
        scOut[c] = sc;
        shOut[c] = beta[c] - mean * sc;
    }
}

// ---------------- fused attention: MUFU exp2, 3-stage K/V, single sync/kt ----------------
// smem halfs: Qh @0 [112][56] (6272), Kh @6272 3x[64][56] (10752), Vh @17024 3x[64][56] (10752)
// floats from idx 13888: bias[784], uRow[112], consts aq/bq/ak/bk/cv/ev 6x[48]
// total = 60288 bytes
__global__ __launch_bounds__(224, 2) void attn_kernel(const __half* __restrict__ Y,
                                                      const float* __restrict__ biases,
                                                      const float* __restrict__ sc1,
                                                      const float* __restrict__ sh1,
                                                      __half* __restrict__ Ohs) {
    extern __shared__ uint32_t sm[];
    float* smf = (float*)sm;
    const int QH = 0, KH = 6272, VH = 17024;
    const int STAGE = 64*56;                 // halfs per K/V stage
    float* biasRow = smf + 13888;            // 784
    float* uRow    = smf + 14672;            // 112
    float* aq = smf + 14784; float* bq = smf + 14832;
    float* ak = smf + 14880; float* bk = smf + 14928;
    float* cv = smf + 14976; float* ev = smf + 15024;

    int t = threadIdx.x;
    int w = t >> 5, L = t & 31;
    int g = L >> 2, c = L & 3;
    int m0l = w * 16;
    int bh = blockIdx.y;
    int b = bh >> 3, h = bh & 7;
    int q0 = blockIdx.x * 112;

    uint32_t base = smem_u32(sm);
    uint32_t kBase = base + KH*2, vBase = base + VH*2;

    #define ISSUE_TILE(kt, stage) { \
        int k0i = (kt) * 64; \
        for (int idx = t; idx < 768; idx += 224) { \
            int hv  = idx >= 384; \
            int rem = idx - hv*384; \
            int row = rem / 6, seg = rem - row*6; \
            int n = k0i + row; if (n > NN-1) n = NN-1; \
            const __half* src = Y + (size_t)(b*NN + n)*INNER + (hv ? 768 : 384) + h*HD + seg*8; \
            uint32_t dst = (hv ? vBase : kBase) + (stage)*STAGE*2 + (row*56 + seg*8)*2; \
            asm volatile("cp.async.ca.shared.global [%0], [%1], 16;" :: "r"(dst), "l"(src)); \
        } \
        asm volatile("cp.async.commit_group;"); }

    ISSUE_TILE(0, 0);
    ISSUE_TILE(1, 1);

    // consts (order: aq,bq,ak,bk,cv,ev)
    for (int i = t; i < 288; i += 224) {
        int which = i / 48, d = i - which*48;
        int p = which >> 1;
        float v = (which & 1) ? sh1[p*CC + h*HD + d] : sc1[p*CC + h*HD + d];
        smf[14784 + which*48 + d] = v;
    }
    for (int i = t; i < NN; i += 224) biasRow[i] = biases[h * NN + i] * 1.4426950408889634f;
    __syncthreads();   // consts ready for Q fold

    const float scale = 0.14433756729740643f;            // 48^-0.5
    const float cs = scale * 1.4426950408889634f;        // *log2(e)

    // ---- Q load + BN fold: q' = q*aq+bq ; t_i = sum q'*bk ; q'' = q'*ak ----
    {
        int row = t >> 1, ds = (t & 1) * 24;
        const __half2* src = (const __half2*)(Y + (size_t)(b*NN + q0 + row)*INNER + h*HD + ds);
        float tpart = 0.f;
        #pragma unroll
        for (int j = 0; j < 12; j++) {
            int d = ds + 2*j;
            float2 f = __half22float2(src[j]);
            float q0f = fmaf(f.x, aq[d],   bq[d]);
            float q1f = fmaf(f.y, aq[d+1], bq[d+1]);
            tpart = fmaf(q0f, bk[d], tpart);
            tpart = fmaf(q1f, bk[d+1], tpart);
            sm[QH/2 + row*28 + ds/2 + j] = pack2(q0f*ak[d], q1f*ak[d+1]);
        }
        tpart += __shfl_xor_sync(0xffffffffu, tpart, 1);
        if ((t & 1) == 0) uRow[row] = cs * tpart;
    }
    __syncthreads();   // Qh + uRow visible

    // hoisted loop-invariant Q fragments
    uint32_t qA = base + QH*2 + ((m0l + (L & 15))*56 + (L >> 4)*8)*2;
    uint32_t qa0[3], qa1[3], qa2[3], qa3[3];
    #pragma unroll
    for (int ks = 0; ks < 3; ks++)
        ldsm4(qa0[ks], qa1[ks], qa2[ks], qa3[ks], qA + ks*32);
    float u0 = uRow[m0l + g];
    float u1 = uRow[m0l + 8 + g];

    // per-thread query coords for bias-index math
    int qr0 = q0 + m0l + g, qr1 = qr0 + 8;
    int xi0 = qr0 / 28, yi0 = qr0 - xi0 * 28;
    int xi1 = qr1 / 28, yi1 = qr1 - xi1 * 28;

    int r8 = L & 7, sel = L >> 3;
    uint32_t kB_rel = (uint32_t)((((sel >> 1)*8 + r8)*56 + (sel & 1)*8)*2);
    uint32_t vB_rel = (uint32_t)((((sel & 1)*8 + r8)*56)*2 + (sel >> 1)*16);

    float Oc[6][4] = {};
    float lsum0 = 0.f, lsum1 = 0.f;

    for (int kt = 0; kt < 13; kt++) {
        int k0 = kt * 64;
        uint32_t so = (kt % 3) * STAGE*2;
        if (kt < 12) asm volatile("cp.async.wait_group 1;");
        else         asm volatile("cp.async.wait_group 0;");
        __syncthreads();
        if (kt + 2 < 13) { ISSUE_TILE(kt + 2, (kt + 2) % 3); }

        // S = Q'' K_raw^T : m16 x n64, k48
        float Sc[8][4] = {};
        #pragma unroll
        for (int ks = 0; ks < 3; ks++) {
            #pragma unroll
            for (int nbp = 0; nbp < 4; nbp++) {
                uint32_t b00, b10, b01, b11;
                ldsm4(b00, b10, b01, b11, kBase + so + nbp*16*112 + ks*32 + kB_rel);
                mma_f16(Sc[2*nbp],   qa0[ks], qa1[ks], qa2[ks], qa3[ks], b00, b10);
                mma_f16(Sc[2*nbp+1], qa0[ks], qa1[ks], qa2[ks], qa3[ks], b01, b11);
            }
        }

        // P = exp2(cs*S + u_i + bias) via MUFU, kept in registers
        float Pv[8][4];
        #pragma unroll
        for (int nb = 0; nb < 8; nb++) {
            int col0 = nb*8 + 2*c;
            int kj = k0 + col0;
            float p0 = 0.f, p1 = 0.f, p2 = 0.f, p3 = 0.f;
            if (kj < NN) {
                int xj = kj / 28, yj = kj - xj * 28;
                float b0v = biasRow[abs(xi0 - xj)*28 + abs(yi0 - yj)];
                float b2v = biasRow[abs(xi1 - xj)*28 + abs(yi1 - yj)];
                p0 = ex2(fmaf(Sc[nb][0], cs, u0 + b0v));
                p2 = ex2(fmaf(Sc[nb][2], cs, u1 + b2v));
            }
            if (kj + 1 < NN) {
                int kj1 = kj + 1;
                int xj = kj1 / 28, yj = kj1 - xj * 28;
                float b1v = biasRow[abs(xi0 - xj)*28 + abs(yi0 - yj)];
                float b3v = biasRow[abs(xi1 - xj)*28 + abs(yi1 - yj)];
                p1 = ex2(fmaf(Sc[nb][1], cs, u0 + b1v));
                p3 = ex2(fmaf(Sc[nb][3], cs, u1 + b3v));
            }
            Pv[nb][0] = p0; Pv[nb][1] = p1; Pv[nb][2] = p2; Pv[nb][3] = p3;
            lsum0 += p0 + p1; lsum1 += p2 + p3;
        }

        // O += P V_raw : P fed directly from registers (acc layout == A-frag layout)
        #pragma unroll
        for (int ks = 0; ks < 4; ks++) {
            uint32_t a0 = pack2(Pv[2*ks][0],   Pv[2*ks][1]);
            uint32_t a1 = pack2(Pv[2*ks][2],   Pv[2*ks][3]);
            uint32_t a2 = pack2(Pv[2*ks+1][0], Pv[2*ks+1][1]);
            uint32_t a3 = pack2(Pv[2*ks+1][2], Pv[2*ks+1][3]);
            #pragma unroll
            for (int nbp = 0; nbp < 3; nbp++) {
                uint32_t b00, b10, b01, b11;
                ldsm4t(b00, b10, b01, b11, vBase + so + ks*16*112 + nbp*32 + vB_rel);
                mma_f16(Oc[2*nbp],   a0, a1, a2, a3, b00, b10);
                mma_f16(Oc[2*nbp+1], a0, a1, a2, a3, b01, b11);
            }
        }
    }
    #undef ISSUE_TILE

    // row-sum reduce across the 4 c-lanes (same g)
    lsum0 += __shfl_xor_sync(0xffffffffu, lsum0, 1);
    lsum0 += __shfl_xor_sync(0xffffffffu, lsum0, 2);
    lsum1 += __shfl_xor_sync(0xffffffffu, lsum1, 1);
    lsum1 += __shfl_xor_sync(0xffffffffu, lsum1, 2);

    // epilogue: o = cv*(PV/ls) + ev -> hardswish -> fp16
    float inv0 = 1.0f / lsum0;
    float inv1 = 1.0f / lsum1;
    int n0g = q0 + m0l + g, n1g = n0g + 8;
    __half2* O2 = (__half2*)Ohs;
    #pragma unroll
    for (int nb = 0; nb < 6; nb++) {
        int d = nb*8 + 2*c;
        float o00 = fmaf(Oc[nb][0]*inv0, cv[d],   ev[d]);
        float o01 = fmaf(Oc[nb][1]*inv0, cv[d+1], ev[d+1]);
        float o10 = fmaf(Oc[nb][2]*inv1, cv[d],   ev[d]);
        float o11 = fmaf(Oc[nb][3]*inv1, cv[d+1], ev[d+1]);
        O2[((size_t)(b*NN + n0g)*CC + h*HD + d) >> 1] = __floats2half2_rn(hswish(o00), hswish(o01));
        O2[((size_t)(b*NN + n1g)*CC + h*HD + d) >> 1] = __floats2half2_rn(hswish(o10), hswish(o11));
    }
}

// ---------------- final BN apply ----------------
__global__ __launch_bounds__(256) void apply_bn(const float* __restrict__ Z,
                                                const float* __restrict__ sc,
                                                const float* __restrict__ sh,
                                                float* __restrict__ out) {
    size_t base = ((size_t)blockIdx.x * 256 + threadIdx.x) * 4;
    if (base < (size_t)MM * CC) {
        float4 z = *(const float4*)(Z + base);
        int c = (int)(base % CC);
        float4 o;
        o.x = z.x * sc[c+0] + sh[c+0];
        o.y = z.y * sc[c+1] + sh[c+1];
        o.z = z.z * sc[c+2] + sh[c+2];
        o.w = z.w * sc[c+3] + sh[c+3];
        *(float4*)(out + base) = o;
    }
}

extern "C" void kernel_launch(void* const* d_in, const int* in_sizes, int n_in,
                              void* d_out, int out_size) {
    const float* x      = (const float*)d_in[0];
    const float* Wqkv   = (const float*)d_in[1];
    const float* g1     = (const float*)d_in[2];
    const float* b1     = (const float*)d_in[3];
    const float* Wproj  = (const float*)d_in[4];
    const float* g2     = (const float*)d_in[5];
    const float* b2     = (const float*)d_in[6];
    const float* biases = (const float*)d_in[7];
    float* out = (float*)d_out;

    __half *xh, *wqh, *wph, *yh, *ohsh;
    float *sc1, *sh1, *zp, *sc2, *sh2;
    cudaGetSymbolAddress((void**)&xh,   g_xh);
    cudaGetSymbolAddress((void**)&wqh,  g_wqh);
    cudaGetSymbolAddress((void**)&wph,  g_wph);
    cudaGetSymbolAddress((void**)&yh,   g_yh);
    cudaGetSymbolAddress((void**)&sc1,  g_sc1);
    cudaGetSymbolAddress((void**)&sh1,  g_sh1);
    cudaGetSymbolAddress((void**)&ohsh, g_ohsh);
    cudaGetSymbolAddress((void**)&zp,   g_z);
    cudaGetSymbolAddress((void**)&sc2,  g_sc2);
    cudaGetSymbolAddress((void**)&sh2,  g_sh2);

    cudaFuncSetAttribute(gemm_cp<1>, cudaFuncAttributeMaxDynamicSharedMemorySize, 61440);
    cudaFuncSetAttribute(gemm_cp<0>, cudaFuncAttributeMaxDynamicSharedMemorySize, 61440);
    cudaFuncSetAttribute(attn_kernel, cudaFuncAttributeMaxDynamicSharedMemorySize, 60288);

    f2h<<<(MM*CC/4 + 255)/256, 256>>>(x, xh, MM*CC/4);
    f2h<<<(INNER*CC/4 + 255)/256, 256>>>(Wqkv, wqh, INNER*CC/4);
    f2h<<<(CC*CC/4 + 255)/256, 256>>>(Wproj, wph, CC*CC/4);

    gemm_cp<1><<<dim3(INNER/128, MM/128), 256, 61440>>>(xh, wqh, yh, INNER);
    colstats_h<<<INNER/64, 256>>>(yh, INNER, g1, b1, sc1, sh1);
    attn_kernel<<<dim3(7, BB*HH), 224, 60288>>>(yh, biases, sc1, sh1, ohsh);
    gemm_cp<0><<<dim3(CC/128, MM/128), 256, 61440>>>(ohsh, wph, zp, CC);
    colstats_f<<<CC/32, 256>>>(zp, CC, g2, b2, sc2, sh2);
    apply_bn<<<(MM*CC/4 + 255)/256, 256>>>(zp, sc2, sh2, out);
}

// round 10
// speedup vs baseline: 2.0497x; 1.0287x over previous
#include <cuda_runtime.h>
#include <cuda_fp16.h>
#include <math.h>
#include <stdint.h>

#define BB 16
#define NN 784
#define CC 384
#define HH 8
#define HD 48
#define INNER 1152
#define MM (BB*NN)          // 12544
#define EPSV 1e-5f

// ---------------- scratch ----------------
__device__ __half g_xh[(size_t)MM * CC];
__device__ __half g_wqh[(size_t)INNER * CC];
__device__ __half g_wph[(size_t)CC * CC];
__device__ __half g_yh[(size_t)MM * INNER];     // qkv pre-norm, fp16 (28.9 MB)
__device__ float  g_sc1[INNER];
__device__ float  g_sh1[INNER];
__device__ __half g_ohsh[(size_t)MM * CC];      // hardswish(attn out), fp16
__device__ float  g_z[(size_t)MM * CC];         // proj pre-norm, fp32
__device__ float  g_sc2[CC];
__device__ float  g_sh2[CC];
__device__ __half g_bg[(size_t)HH * NN * NN + 64];   // pre-gathered bias*log2e, fp16 (9.8 MB)

// ---------------- helpers ----------------
__device__ __forceinline__ uint32_t pack2(float a, float b) {
    __half2 h = __floats2half2_rn(a, b);
    return *reinterpret_cast<uint32_t*>(&h);
}
__device__ __forceinline__ uint32_t smem_u32(const void* p) {
    return (uint32_t)__cvta_generic_to_shared(p);
}
__device__ __forceinline__ float ex2(float x) {        // MUFU.EX2
    float r;
    asm("ex2.approx.f32 %0, %1;" : "=f"(r) : "f"(x));
    return r;
}
__device__ __forceinline__ void mma_f16(float* c,
        uint32_t a0, uint32_t a1, uint32_t a2, uint32_t a3,
        uint32_t b0, uint32_t b1) {
    asm volatile("mma.sync.aligned.m16n8k16.row.col.f32.f16.f16.f32 "
                 "{%0,%1,%2,%3},{%4,%5,%6,%7},{%8,%9},{%0,%1,%2,%3};"
                 : "+f"(c[0]), "+f"(c[1]), "+f"(c[2]), "+f"(c[3])
                 : "r"(a0), "r"(a1), "r"(a2), "r"(a3), "r"(b0), "r"(b1));
}
__device__ __forceinline__ void ldsm4(uint32_t& r0, uint32_t& r1, uint32_t& r2, uint32_t& r3, uint32_t a) {
    asm volatile("ldmatrix.sync.aligned.m8n8.x4.shared.b16 {%0,%1,%2,%3}, [%4];"
                 : "=r"(r0),"=r"(r1),"=r"(r2),"=r"(r3) : "r"(a));
}
__device__ __forceinline__ void ldsm4t(uint32_t& r0, uint32_t& r1, uint32_t& r2, uint32_t& r3, uint32_t a) {
    asm volatile("ldmatrix.sync.aligned.m8n8.x4.trans.shared.b16 {%0,%1,%2,%3}, [%4];"
                 : "=r"(r0),"=r"(r1),"=r"(r2),"=r"(r3) : "r"(a));
}
__device__ __forceinline__ float hswish(float v) {
    return v * fminf(fmaxf(v + 3.f, 0.f), 6.f) * (1.0f/6.0f);
}

// ---------------- fp32 -> fp16 convert (x, Wqkv, Wproj in one launch) ----------------
#define N4_X   (MM*CC/4)
#define N4_WQ  (INNER*CC/4)
#define N4_WP  (CC*CC/4)
__global__ __launch_bounds__(256) void f2h_all(const float* __restrict__ x,
                                               const float* __restrict__ wq,
                                               const float* __restrict__ wp) {
    int i = blockIdx.x * 256 + threadIdx.x;
    const float* in; __half* out; int idx;
    if (i < N4_X)                { in = x;  out = g_xh;  idx = i; }
    else if (i < N4_X + N4_WQ)   { in = wq; out = g_wqh; idx = i - N4_X; }
    else if (i < N4_X + N4_WQ + N4_WP) { in = wp; out = g_wph; idx = i - N4_X - N4_WQ; }
    else return;
    float4 v = ((const float4*)in)[idx];
    __half2* o = (__half2*)out;
    o[2*idx]   = __floats2half2_rn(v.x, v.y);
    o[2*idx+1] = __floats2half2_rn(v.z, v.w);
}

// ---------------- pre-gather bias: Bg[h][qi][kj] = biases[h][idx(qi,kj)]*log2e, fp16 ----------------
__global__ __launch_bounds__(256) void bias_expand(const float* __restrict__ biases) {
    int qi = blockIdx.x;
    int h  = blockIdx.y;
    __shared__ float br[NN];
    for (int i = threadIdx.x; i < NN; i += 256)
        br[i] = biases[h*NN + i] * 1.4426950408889634f;
    __syncthreads();
    int xi = qi / 28, yi = qi - xi*28;
    __half* dst = g_bg + ((size_t)h*NN + qi) * NN;
    for (int kj = threadIdx.x; kj < NN; kj += 256) {
        int xj = kj / 28, yj = kj - xj*28;
        dst[kj] = __float2half_rn(br[abs(xi-xj)*28 + abs(yi-yj)]);
    }
}

// ---------------- cp.async pipelined fp16 GEMM NT (K=384), ldmatrix frags ----------------
template<int OUTH>
__global__ __launch_bounds__(256) void gemm_cp(const __half* __restrict__ A,
                                               const __half* __restrict__ Bw,
                                               void* __restrict__ C, int Nn) {
    extern __shared__ __half hs[];          // [3][2][128*40]
    const int STG = 128*40;
    int t = threadIdx.x;
    int w = t >> 5, L = t & 31;
    int g = L >> 2, c = L & 3;
    int wm = w & 3, wn = w >> 2;
    int m0 = blockIdx.y * 128, n0 = blockIdx.x * 128;

    int id0 = t, id1 = t + 256;
    int ra0 = id0 >> 2, oa0 = (id0 & 3) * 8;
    int ra1 = id1 >> 2, oa1 = (id1 & 3) * 8;
    const __half* Ap0 = A  + (size_t)(m0 + ra0) * 384 + oa0;
    const __half* Ap1 = A  + (size_t)(m0 + ra1) * 384 + oa1;
    const __half* Bp0 = Bw + (size_t)(n0 + ra0) * 384 + oa0;
    const __half* Bp1 = Bw + (size_t)(n0 + ra1) * 384 + oa1;

    uint32_t base = smem_u32(hs);
    uint32_t dA0 = base + (ra0*40 + oa0)*2;
    uint32_t dA1 = base + (ra1*40 + oa1)*2;
    uint32_t dB0 = base + (STG + ra0*40 + oa0)*2;
    uint32_t dB1 = base + (STG + ra1*40 + oa1)*2;

    int r8 = L & 7, sel = L >> 3;
    uint32_t aAddr = base + ((wm*32 + (L & 15))*40 + (L >> 4)*8)*2;
    uint32_t bAddr = base + STG*2 + ((wn*64 + (sel>>1)*8 + r8)*40 + (sel&1)*8)*2;

    #define ISSUE(st, kc) { \
        int ko = (kc) * 32; uint32_t so = (st) * (2*STG*2); \
        asm volatile("cp.async.ca.shared.global [%0], [%1], 16;" :: "r"(dA0+so), "l"(Ap0+ko)); \
        asm volatile("cp.async.ca.shared.global [%0], [%1], 16;" :: "r"(dA1+so), "l"(Ap1+ko)); \
        asm volatile("cp.async.ca.shared.global [%0], [%1], 16;" :: "r"(dB0+so), "l"(Bp0+ko)); \
        asm volatile("cp.async.ca.shared.global [%0], [%1], 16;" :: "r"(dB1+so), "l"(Bp1+ko)); \
        asm volatile("cp.async.commit_group;"); }

    float acc[2][8][4] = {};
    ISSUE(0, 0); ISSUE(1, 1);

    for (int kc = 0; kc < 12; kc++) {
        if (kc < 11) asm volatile("cp.async.wait_group 1;");
        else         asm volatile("cp.async.wait_group 0;");
        __syncthreads();
        if (kc + 2 < 12) { ISSUE((kc+2)%3, kc+2); }
        uint32_t so = (kc % 3) * (2*STG*2);
        #pragma unroll
        for (int ks = 0; ks < 2; ks++) {
            uint32_t a0[2], a1[2], a2[2], a3[2];
            #pragma unroll
            for (int i = 0; i < 2; i++)
                ldsm4(a0[i], a1[i], a2[i], a3[i], aAddr + so + i*16*80 + ks*32);
            #pragma unroll
            for (int nbp = 0; nbp < 4; nbp++) {
                uint32_t b00, b10, b01, b11;
                ldsm4(b00, b10, b01, b11, bAddr + so + nbp*16*80 + ks*32);
                #pragma unroll
                for (int i = 0; i < 2; i++) {
                    mma_f16(acc[i][2*nbp],   a0[i], a1[i], a2[i], a3[i], b00, b10);
                    mma_f16(acc[i][2*nbp+1], a0[i], a1[i], a2[i], a3[i], b01, b11);
                }
            }
        }
    }
    #undef ISSUE

    #pragma unroll
    for (int i = 0; i < 2; i++) {
        int row = m0 + wm*32 + i*16 + g;
        #pragma unroll
        for (int nb = 0; nb < 8; nb++) {
            int col = n0 + wn*64 + nb*8 + 2*c;
            if (OUTH) {
                __half2* Ch = (__half2*)C;
                Ch[((size_t)row*Nn + col) >> 1]     = __floats2half2_rn(acc[i][nb][0], acc[i][nb][1]);
                Ch[((size_t)(row+8)*Nn + col) >> 1] = __floats2half2_rn(acc[i][nb][2], acc[i][nb][3]);
            } else {
                float* Cf = (float*)C;
                *(float2*)(Cf + (size_t)row*Nn + col)     = make_float2(acc[i][nb][0], acc[i][nb][1]);
                *(float2*)(Cf + (size_t)(row+8)*Nn + col) = make_float2(acc[i][nb][2], acc[i][nb][3]);
            }
        }
    }
}

// ---------------- column stats, fp16 input ----------------
__global__ __launch_bounds__(256) void colstats_h(const __half* __restrict__ Y, int Ncol,
                                                  const float* __restrict__ gamma,
                                                  const float* __restrict__ beta,
                                                  float* __restrict__ scOut,
                                                  float* __restrict__ shOut) {
    int lc = threadIdx.x & 31;
    int rg = threadIdx.x >> 5;
    int cp = blockIdx.x * 32 + lc;
    const __half2* Y2 = (const __half2*)Y;
    int stride = Ncol >> 1;
    float sx = 0.f, sx2 = 0.f, sy = 0.f, sy2 = 0.f;
    for (int r = rg; r < MM; r += 8) {
        float2 f = __half22float2(Y2[(size_t)r * stride + cp]);
        sx += f.x; sx2 += f.x*f.x; sy += f.y; sy2 += f.y*f.y;
    }
    __shared__ float sA[8][32], sB[8][32], sC2[8][32], sD[8][32];
    sA[rg][lc] = sx; sB[rg][lc] = sx2; sC2[rg][lc] = sy; sD[rg][lc] = sy2;
    __syncthreads();
    if (rg == 0) {
        #pragma unroll
        for (int gg = 1; gg < 8; gg++) {
            sx += sA[gg][lc]; sx2 += sB[gg][lc]; sy += sC2[gg][lc]; sy2 += sD[gg][lc];
        }
        int c0 = 2*cp, c1 = 2*cp + 1;
        float m0 = sx * (1.0f/MM), m1 = sy * (1.0f/MM);
        float v0 = sx2 * (1.0f/MM) - m0*m0;
        float v1 = sy2 * (1.0f/MM) - m1*m1;
        float s0 = gamma[c0] * rsqrtf(v0 + EPSV);
        float s1 = gamma[c1] * rsqrtf(v1 + EPSV);
        scOut[c0] = s0; shOut[c0] = beta[c0] - m0*s0;
        scOut[c1] = s1; shOut[c1] = beta[c1] - m1*s1;
    }
}

// ---------------- column stats, fp32 input ----------------
__global__ __launch_bounds__(256) void colstats_f(const float* __restrict__ Y, int Ncol,
                                                  const float* __restrict__ gamma,
                                                  const float* __restrict__ beta,
                                                  float* __restrict__ scOut,
                                                  float* __restrict__ shOut) {
    int lc = threadIdx.x & 31;
    int rg = threadIdx.x >> 5;
    int c  = blockIdx.x * 32 + lc;
    float s = 0.f, s2 = 0.f;
    for (int r = rg; r < MM; r += 8) {
        float v = Y[(size_t)r * Ncol + c];
        s += v; s2 += v * v;
    }
    __shared__ float sh[8][32], sh2[8][32];
    sh[rg][lc] = s; sh2[rg][lc] = s2;
    __syncthreads();
    if (rg == 0) {
        #pragma unroll
        for (int gg = 1; gg < 8; gg++) { s += sh[gg][lc]; s2 += sh2[gg][lc]; }
        float mean = s * (1.0f / MM);
        float var  = s2 * (1.0f / MM) - mean * mean;
        float sc   = gamma[c] * rsqrtf(var + EPSV);
        scOut[c] = sc;
        shOut[c] = beta[c] - mean * sc;
    }
}

// ---------------- fused attention: pre-gathered bias tile via cp.async ----------------
// smem halfs: Qh @0 [112][56] (6272), Kh @6272 3x[64][56] (10752), Vh @17024 3x[64][56] (10752),
//             Bh @27776 3x[112][72] (24192)  -> ends 51968 halfs
// floats from word 25984: uRow[112], consts aq/bq/ak/bk/cv/ev 6x[48]
// total = 105536 bytes
__global__ __launch_bounds__(224, 2) void attn_kernel(const __half* __restrict__ Y,
                                                      const __half* __restrict__ Bg,
                                                      const float* __restrict__ sc1,
                                                      const float* __restrict__ sh1,
                                                      __half* __restrict__ Ohs) {
    extern __shared__ uint32_t sm[];
    float* smf = (float*)sm;
    const int QH = 0, KH = 6272, VH = 17024, BH = 27776;
    const int STAGE = 64*56;                 // halfs per K/V stage
    const int BSTG  = 112*72;                // halfs per bias stage
    float* uRow = smf + 25984;               // 112
    float* aq = smf + 26096; float* bq = smf + 26144;
    float* ak = smf + 26192; float* bk = smf + 26240;
    float* cv = smf + 26288; float* ev = smf + 26336;

    int t = threadIdx.x;
    int w = t >> 5, L = t & 31;
    int g = L >> 2, c = L & 3;
    int m0l = w * 16;
    int bh = blockIdx.y;
    int b = bh >> 3, h = bh & 7;
    int q0 = blockIdx.x * 112;

    uint32_t base = smem_u32(sm);
    uint32_t kBase = base + KH*2, vBase = base + VH*2, bBase = base + BH*2;
    const __half* BgRow = Bg + ((size_t)h*NN + q0) * NN;   // row-major [112 rows][784]

    #define ISSUE_TILE(kt, stage) { \
        int k0i = (kt) * 64; \
        for (int idx = t; idx < 1664; idx += 224) { \
            if (idx < 768) { \
                int hv  = idx >= 384; \
                int rem = idx - hv*384; \
                int row = rem / 6, seg = rem - row*6; \
                int n = k0i + row; if (n > NN-1) n = NN-1; \
                const __half* src = Y + (size_t)(b*NN + n)*INNER + (hv ? 768 : 384) + h*HD + seg*8; \
                uint32_t dst = (hv ? vBase : kBase) + (stage)*STAGE*2 + (row*56 + seg*8)*2; \
                asm volatile("cp.async.ca.shared.global [%0], [%1], 16;" :: "r"(dst), "l"(src)); \
            } else { \
                int ib = idx - 768; \
                int row = ib >> 3, seg = ib & 7; \
                const __half* src = BgRow + (size_t)row*NN + k0i + seg*8; \
                uint32_t dst = bBase + (stage)*BSTG*2 + (row*72 + seg*8)*2; \
                asm volatile("cp.async.ca.shared.global [%0], [%1], 16;" :: "r"(dst), "l"(src)); \
            } \
        } \
        asm volatile("cp.async.commit_group;"); }

    ISSUE_TILE(0, 0);
    ISSUE_TILE(1, 1);

    // consts (order: aq,bq,ak,bk,cv,ev)
    for (int i = t; i < 288; i += 224) {
        int which = i / 48, d = i - which*48;
        int p = which >> 1;
        float v = (which & 1) ? sh1[p*CC + h*HD + d] : sc1[p*CC + h*HD + d];
        smf[26096 + which*48 + d] = v;
    }
    __syncthreads();   // consts ready for Q fold

    const float scale = 0.14433756729740643f;            // 48^-0.5
    const float cs = scale * 1.4426950408889634f;        // *log2(e)

    // ---- Q load + BN fold: q' = q*aq+bq ; t_i = sum q'*bk ; q'' = q'*ak ----
    {
        int row = t >> 1, ds = (t & 1) * 24;
        const __half2* src = (const __half2*)(Y + (size_t)(b*NN + q0 + row)*INNER + h*HD + ds);
        float tpart = 0.f;
        #pragma unroll
        for (int j = 0; j < 12; j++) {
            int d = ds + 2*j;
            float2 f = __half22float2(src[j]);
            float q0f = fmaf(f.x, aq[d],   bq[d]);
            float q1f = fmaf(f.y, aq[d+1], bq[d+1]);
            tpart = fmaf(q0f, bk[d], tpart);
            tpart = fmaf(q1f, bk[d+1], tpart);
            sm[QH/2 + row*28 + ds/2 + j] = pack2(q0f*ak[d], q1f*ak[d+1]);
        }
        tpart += __shfl_xor_sync(0xffffffffu, tpart, 1);
        if ((t & 1) == 0) uRow[row] = cs * tpart;
    }
    __syncthreads();   // Qh + uRow visible

    // hoisted loop-invariant Q fragments
    uint32_t qA = base + QH*2 + ((m0l + (L & 15))*56 + (L >> 4)*8)*2;
    uint32_t qa0[3], qa1[3], qa2[3], qa3[3];
    #pragma unroll
    for (int ks = 0; ks < 3; ks++)
        ldsm4(qa0[ks], qa1[ks], qa2[ks], qa3[ks], qA + ks*32);
    float u0 = uRow[m0l + g];
    float u1 = uRow[m0l + 8 + g];

    int r8 = L & 7, sel = L >> 3;
    uint32_t kB_rel = (uint32_t)((((sel >> 1)*8 + r8)*56 + (sel & 1)*8)*2);
    uint32_t vB_rel = (uint32_t)((((sel & 1)*8 + r8)*56)*2 + (sel >> 1)*16);

    // bias tile word bases for this thread's two rows (word units)
    int bw0 = BH/2 + (m0l + g)*36 + c;
    int bw1 = BH/2 + (m0l + 8 + g)*36 + c;

    float Oc[6][4] = {};
    float lsum0 = 0.f, lsum1 = 0.f;

    for (int kt = 0; kt < 13; kt++) {
        int k0 = kt * 64;
        uint32_t so  = (kt % 3) * STAGE*2;
        int sob = (kt % 3) * BSTG / 2;         // bias stage offset in words
        if (kt < 12) asm volatile("cp.async.wait_group 1;");
        else         asm volatile("cp.async.wait_group 0;");
        __syncthreads();
        if (kt + 2 < 13) { ISSUE_TILE(kt + 2, (kt + 2) % 3); }

        // S = Q'' K_raw^T : m16 x n64, k48
        float Sc[8][4] = {};
        #pragma unroll
        for (int ks = 0; ks < 3; ks++) {
            #pragma unroll
            for (int nbp = 0; nbp < 4; nbp++) {
                uint32_t b00, b10, b01, b11;
                ldsm4(b00, b10, b01, b11, kBase + so + nbp*16*112 + ks*32 + kB_rel);
                mma_f16(Sc[2*nbp],   qa0[ks], qa1[ks], qa2[ks], qa3[ks], b00, b10);
                mma_f16(Sc[2*nbp+1], qa0[ks], qa1[ks], qa2[ks], qa3[ks], b01, b11);
            }
        }

        // P = exp2(cs*S + u_i + bias) — bias from pre-gathered smem tile
        float Pv[8][4];
        #pragma unroll
        for (int nb = 0; nb < 8; nb++) {
            int kj = k0 + nb*8 + 2*c;
            float p0 = 0.f, p1 = 0.f, p2 = 0.f, p3 = 0.f;
            float2 bf0 = __half22float2(*(const __half2*)&sm[sob + bw0 + nb*4]);
            float2 bf1 = __half22float2(*(const __half2*)&sm[sob + bw1 + nb*4]);
            if (kj < NN) {
                p0 = ex2(fmaf(Sc[nb][0], cs, u0 + bf0.x));
                p2 = ex2(fmaf(Sc[nb][2], cs, u1 + bf1.x));
            }
            if (kj + 1 < NN) {
                p1 = ex2(fmaf(Sc[nb][1], cs, u0 + bf0.y));
                p3 = ex2(fmaf(Sc[nb][3], cs, u1 + bf1.y));
            }
            Pv[nb][0] = p0; Pv[nb][1] = p1; Pv[nb][2] = p2; Pv[nb][3] = p3;
            lsum0 += p0 + p1; lsum1 += p2 + p3;
        }

        // O += P V_raw : P fed directly from registers
        #pragma unroll
        for (int ks = 0; ks < 4; ks++) {
            uint32_t a0 = pack2(Pv[2*ks][0],   Pv[2*ks][1]);
            uint32_t a1 = pack2(Pv[2*ks][2],   Pv[2*ks][3]);
            uint32_t a2 = pack2(Pv[2*ks+1][0], Pv[2*ks+1][1]);
            uint32_t a3 = pack2(Pv[2*ks+1][2], Pv[2*ks+1][3]);
            #pragma unroll
            for (int nbp = 0; nbp < 3; nbp++) {
                uint32_t b00, b10, b01, b11;
                ldsm4t(b00, b10, b01, b11, vBase + so + ks*16*112 + nbp*32 + vB_rel);
                mma_f16(Oc[2*nbp],   a0, a1, a2, a3, b00, b10);
                mma_f16(Oc[2*nbp+1], a0, a1, a2, a3, b01, b11);
            }
        }
    }
    #undef ISSUE_TILE

    // row-sum reduce across the 4 c-lanes (same g)
    lsum0 += __shfl_xor_sync(0xffffffffu, lsum0, 1);
    lsum0 += __shfl_xor_sync(0xffffffffu, lsum0, 2);
    lsum1 += __shfl_xor_sync(0xffffffffu, lsum1, 1);
    lsum1 += __shfl_xor_sync(0xffffffffu, lsum1, 2);

    // epilogue: o = cv*(PV/ls) + ev -> hardswish -> fp16
    float inv0 = 1.0f / lsum0;
    float inv1 = 1.0f / lsum1;
    int n0g = q0 + m0l + g, n1g = n0g + 8;
    __half2* O2 = (__half2*)Ohs;
    #pragma unroll
    for (int nb = 0; nb < 6; nb++) {
        int d = nb*8 + 2*c;
        float o00 = fmaf(Oc[nb][0]*inv0, cv[d],   ev[d]);
        float o01 = fmaf(Oc[nb][1]*inv0, cv[d+1], ev[d+1]);
        float o10 = fmaf(Oc[nb][2]*inv1, cv[d],   ev[d]);
        float o11 = fmaf(Oc[nb][3]*inv1, cv[d+1], ev[d+1]);
        O2[((size_t)(b*NN + n0g)*CC + h*HD + d) >> 1] = __floats2half2_rn(hswish(o00), hswish(o01));
        O2[((size_t)(b*NN + n1g)*CC + h*HD + d) >> 1] = __floats2half2_rn(hswish(o10), hswish(o11));
    }
}

// ---------------- final BN apply ----------------
__global__ __launch_bounds__(256) void apply_bn(const float* __restrict__ Z,
                                                const float* __restrict__ sc,
                                                const float* __restrict__ sh,
                                                float* __restrict__ out) {
    size_t base = ((size_t)blockIdx.x * 256 + threadIdx.x) * 4;
    if (base < (size_t)MM * CC) {
        float4 z = *(const float4*)(Z + base);
        int c = (int)(base % CC);
        float4 o;
        o.x = z.x * sc[c+0] + sh[c+0];
        o.y = z.y * sc[c+1] + sh[c+1];
        o.z = z.z * sc[c+2] + sh[c+2];
        o.w = z.w * sc[c+3] + sh[c+3];
        *(float4*)(out + base) = o;
    }
}

extern "C" void kernel_launch(void* const* d_in, const int* in_sizes, int n_in,
                              void* d_out, int out_size) {
    const float* x      = (const float*)d_in[0];
    const float* Wqkv   = (const float*)d_in[1];
    const float* g1     = (const float*)d_in[2];
    const float* b1     = (const float*)d_in[3];
    const float* Wproj  = (const float*)d_in[4];
    const float* g2     = (const float*)d_in[5];
    const float* b2     = (const float*)d_in[6];
    const float* biases = (const float*)d_in[7];
    float* out = (float*)d_out;

    __half *xh, *wqh, *wph, *yh, *ohsh, *bg;
    float *sc1, *sh1, *zp, *sc2, *sh2;
    cudaGetSymbolAddress((void**)&xh,   g_xh);
    cudaGetSymbolAddress((void**)&wqh,  g_wqh);
    cudaGetSymbolAddress((void**)&wph,  g_wph);
    cudaGetSymbolAddress((void**)&yh,   g_yh);
    cudaGetSymbolAddress((void**)&sc1,  g_sc1);
    cudaGetSymbolAddress((void**)&sh1,  g_sh1);
    cudaGetSymbolAddress((void**)&ohsh, g_ohsh);
    cudaGetSymbolAddress((void**)&zp,   g_z);
    cudaGetSymbolAddress((void**)&sc2,  g_sc2);
    cudaGetSymbolAddress((void**)&sh2,  g_sh2);
    cudaGetSymbolAddress((void**)&bg,   g_bg);

    cudaFuncSetAttribute(gemm_cp<1>, cudaFuncAttributeMaxDynamicSharedMemorySize, 61440);
    cudaFuncSetAttribute(gemm_cp<0>, cudaFuncAttributeMaxDynamicSharedMemorySize, 61440);
    cudaFuncSetAttribute(attn_kernel, cudaFuncAttributeMaxDynamicSharedMemorySize, 105536);

    int n4all = N4_X + N4_WQ + N4_WP;
    f2h_all<<<(n4all + 255)/256, 256>>>(x, Wqkv, Wproj);
    bias_expand<<<dim3(NN, HH), 256>>>(biases);

    gemm_cp<1><<<dim3(INNER/128, MM/128), 256, 61440>>>(xh, wqh, yh, INNER);
    colstats_h<<<INNER/64, 256>>>(yh, INNER, g1, b1, sc1, sh1);
    attn_kernel<<<dim3(7, BB*HH), 224, 105536>>>(yh, bg, sc1, sh1, ohsh);
    gemm_cp<0><<<dim3(CC/128, MM/128), 256, 61440>>>(ohsh, wph, zp, CC);
    colstats_f<<<CC/32, 256>>>(zp, CC, g2, b2, sc2, sh2);
    apply_bn<<<(MM*CC/4 + 255)/256, 256>>>(zp, sc2, sh2, out);
}

// round 11
// speedup vs baseline: 3.0361x; 1.4812x over previous
#include <cuda_runtime.h>
#include <cuda_fp16.h>
#include <math.h>
#include <stdint.h>

#define BB 16
#define NN 784
#define CC 384
#define HH 8
#define HD 48
#define INNER 1152
#define MM (BB*NN)          // 12544
#define EPSV 1e-5f
#define RG 49               // row groups (49*256 = 12544)

// ---------------- scratch ----------------
__device__ __half g_xh[(size_t)MM * CC];
__device__ __half g_wqh[(size_t)INNER * CC];
__device__ __half g_wph[(size_t)CC * CC];
__device__ __half g_yh[(size_t)MM * INNER];     // qkv pre-norm, fp16 (28.9 MB)
__device__ float  g_sc1[INNER];
__device__ float  g_sh1[INNER];
__device__ __half g_ohsh[(size_t)MM * CC];      // hardswish(attn out), fp16
__device__ float  g_z[(size_t)MM * CC];         // proj pre-norm, fp32
__device__ float  g_sc2[CC];
__device__ float  g_sh2[CC];
__device__ __half g_bg[(size_t)HH * NN * NN + 64];   // pre-gathered bias*log2e, fp16
__device__ float  g_ps1[2][INNER];              // BN1 partial sums (sum, sumsq)
__device__ float  g_ps2[2][CC];                 // BN2 partial sums

// ---------------- helpers ----------------
__device__ __forceinline__ uint32_t pack2(float a, float b) {
    __half2 h = __floats2half2_rn(a, b);
    return *reinterpret_cast<uint32_t*>(&h);
}
__device__ __forceinline__ uint32_t smem_u32(const void* p) {
    return (uint32_t)__cvta_generic_to_shared(p);
}
__device__ __forceinline__ float ex2(float x) {        // MUFU.EX2
    float r;
    asm("ex2.approx.f32 %0, %1;" : "=f"(r) : "f"(x));
    return r;
}
__device__ __forceinline__ void mma_f16(float* c,
        uint32_t a0, uint32_t a1, uint32_t a2, uint32_t a3,
        uint32_t b0, uint32_t b1) {
    asm volatile("mma.sync.aligned.m16n8k16.row.col.f32.f16.f16.f32 "
                 "{%0,%1,%2,%3},{%4,%5,%6,%7},{%8,%9},{%0,%1,%2,%3};"
                 : "+f"(c[0]), "+f"(c[1]), "+f"(c[2]), "+f"(c[3])
                 : "r"(a0), "r"(a1), "r"(a2), "r"(a3), "r"(b0), "r"(b1));
}
__device__ __forceinline__ void ldsm4(uint32_t& r0, uint32_t& r1, uint32_t& r2, uint32_t& r3, uint32_t a) {
    asm volatile("ldmatrix.sync.aligned.m8n8.x4.shared.b16 {%0,%1,%2,%3}, [%4];"
                 : "=r"(r0),"=r"(r1),"=r"(r2),"=r"(r3) : "r"(a));
}
__device__ __forceinline__ void ldsm4t(uint32_t& r0, uint32_t& r1, uint32_t& r2, uint32_t& r3, uint32_t a) {
    asm volatile("ldmatrix.sync.aligned.m8n8.x4.trans.shared.b16 {%0,%1,%2,%3}, [%4];"
                 : "=r"(r0),"=r"(r1),"=r"(r2),"=r"(r3) : "r"(a));
}
__device__ __forceinline__ float hswish(float v) {
    return v * fminf(fmaxf(v + 3.f, 0.f), 6.f) * (1.0f/6.0f);
}

// ---------------- zero partial-sum buffers (graph-replay safe) ----------------
__global__ __launch_bounds__(256) void zero_ps() {
    int i = blockIdx.x * 256 + threadIdx.x;
    if (i < 2*INNER) ((float*)g_ps1)[i] = 0.f;
    else if (i < 2*INNER + 2*CC) ((float*)g_ps2)[i - 2*INNER] = 0.f;
}

// ---------------- fp32 -> fp16 convert (x, Wqkv, Wproj in one launch) ----------------
#define N4_X   (MM*CC/4)
#define N4_WQ  (INNER*CC/4)
#define N4_WP  (CC*CC/4)
__global__ __launch_bounds__(256) void f2h_all(const float* __restrict__ x,
                                               const float* __restrict__ wq,
                                               const float* __restrict__ wp) {
    int i = blockIdx.x * 256 + threadIdx.x;
    const float* in; __half* out; int idx;
    if (i < N4_X)                { in = x;  out = g_xh;  idx = i; }
    else if (i < N4_X + N4_WQ)   { in = wq; out = g_wqh; idx = i - N4_X; }
    else if (i < N4_X + N4_WQ + N4_WP) { in = wp; out = g_wph; idx = i - N4_X - N4_WQ; }
    else return;
    float4 v = ((const float4*)in)[idx];
    __half2* o = (__half2*)out;
    o[2*idx]   = __floats2half2_rn(v.x, v.y);
    o[2*idx+1] = __floats2half2_rn(v.z, v.w);
}

// ---------------- pre-gather bias ----------------
__global__ __launch_bounds__(256) void bias_expand(const float* __restrict__ biases) {
    int qi = blockIdx.x;
    int h  = blockIdx.y;
    __shared__ float br[NN];
    for (int i = threadIdx.x; i < NN; i += 256)
        br[i] = biases[h*NN + i] * 1.4426950408889634f;
    __syncthreads();
    int xi = qi / 28, yi = qi - xi*28;
    __half* dst = g_bg + ((size_t)h*NN + qi) * NN;
    for (int kj = threadIdx.x; kj < NN; kj += 256) {
        int xj = kj / 28, yj = kj - xj*28;
        dst[kj] = __float2half_rn(br[abs(xi-xj)*28 + abs(yi-yj)]);
    }
}

// ---------------- cp.async pipelined fp16 GEMM NT (K=384) ----------------
template<int OUTH>
__global__ __launch_bounds__(256) void gemm_cp(const __half* __restrict__ A,
                                               const __half* __restrict__ Bw,
                                               void* __restrict__ C, int Nn) {
    extern __shared__ __half hs[];          // [3][2][128*40]
    const int STG = 128*40;
    int t = threadIdx.x;
    int w = t >> 5, L = t & 31;
    int g = L >> 2, c = L & 3;
    int wm = w & 3, wn = w >> 2;
    int m0 = blockIdx.y * 128, n0 = blockIdx.x * 128;

    int id0 = t, id1 = t + 256;
    int ra0 = id0 >> 2, oa0 = (id0 & 3) * 8;
    int ra1 = id1 >> 2, oa1 = (id1 & 3) * 8;
    const __half* Ap0 = A  + (size_t)(m0 + ra0) * 384 + oa0;
    const __half* Ap1 = A  + (size_t)(m0 + ra1) * 384 + oa1;
    const __half* Bp0 = Bw + (size_t)(n0 + ra0) * 384 + oa0;
    const __half* Bp1 = Bw + (size_t)(n0 + ra1) * 384 + oa1;

    uint32_t base = smem_u32(hs);
    uint32_t dA0 = base + (ra0*40 + oa0)*2;
    uint32_t dA1 = base + (ra1*40 + oa1)*2;
    uint32_t dB0 = base + (STG + ra0*40 + oa0)*2;
    uint32_t dB1 = base + (STG + ra1*40 + oa1)*2;

    int r8 = L & 7, sel = L >> 3;
    uint32_t aAddr = base + ((wm*32 + (L & 15))*40 + (L >> 4)*8)*2;
    uint32_t bAddr = base + STG*2 + ((wn*64 + (sel>>1)*8 + r8)*40 + (sel&1)*8)*2;

    #define ISSUE(st, kc) { \
        int ko = (kc) * 32; uint32_t so = (st) * (2*STG*2); \
        asm volatile("cp.async.ca.shared.global [%0], [%1], 16;" :: "r"(dA0+so), "l"(Ap0+ko)); \
        asm volatile("cp.async.ca.shared.global [%0], [%1], 16;" :: "r"(dA1+so), "l"(Ap1+ko)); \
        asm volatile("cp.async.ca.shared.global [%0], [%1], 16;" :: "r"(dB0+so), "l"(Bp0+ko)); \
        asm volatile("cp.async.ca.shared.global [%0], [%1], 16;" :: "r"(dB1+so), "l"(Bp1+ko)); \
        asm volatile("cp.async.commit_group;"); }

    float acc[2][8][4] = {};
    ISSUE(0, 0); ISSUE(1, 1);

    for (int kc = 0; kc < 12; kc++) {
        if (kc < 11) asm volatile("cp.async.wait_group 1;");
        else         asm volatile("cp.async.wait_group 0;");
        __syncthreads();
        if (kc + 2 < 12) { ISSUE((kc+2)%3, kc+2); }
        uint32_t so = (kc % 3) * (2*STG*2);
        #pragma unroll
        for (int ks = 0; ks < 2; ks++) {
            uint32_t a0[2], a1[2], a2[2], a3[2];
            #pragma unroll
            for (int i = 0; i < 2; i++)
                ldsm4(a0[i], a1[i], a2[i], a3[i], aAddr + so + i*16*80 + ks*32);
            #pragma unroll
            for (int nbp = 0; nbp < 4; nbp++) {
                uint32_t b00, b10, b01, b11;
                ldsm4(b00, b10, b01, b11, bAddr + so + nbp*16*80 + ks*32);
                #pragma unroll
                for (int i = 0; i < 2; i++) {
                    mma_f16(acc[i][2*nbp],   a0[i], a1[i], a2[i], a3[i], b00, b10);
                    mma_f16(acc[i][2*nbp+1], a0[i], a1[i], a2[i], a3[i], b01, b11);
                }
            }
        }
    }
    #undef ISSUE

    #pragma unroll
    for (int i = 0; i < 2; i++) {
        int row = m0 + wm*32 + i*16 + g;
        #pragma unroll
        for (int nb = 0; nb < 8; nb++) {
            int col = n0 + wn*64 + nb*8 + 2*c;
            if (OUTH) {
                __half2* Ch = (__half2*)C;
                Ch[((size_t)row*Nn + col) >> 1]     = __floats2half2_rn(acc[i][nb][0], acc[i][nb][1]);
                Ch[((size_t)(row+8)*Nn + col) >> 1] = __floats2half2_rn(acc[i][nb][2], acc[i][nb][3]);
            } else {
                float* Cf = (float*)C;
                *(float2*)(Cf + (size_t)row*Nn + col)     = make_float2(acc[i][nb][0], acc[i][nb][1]);
                *(float2*)(Cf + (size_t)(row+8)*Nn + col) = make_float2(acc[i][nb][2], acc[i][nb][3]);
            }
        }
    }
}

// ---------------- split-row column stats, fp16 input ----------------
// grid (Ncol/64, RG). Each block: 32 col-pairs x 256 rows.
__global__ __launch_bounds__(256) void colstats_part_h(const __half* __restrict__ Y, int Ncol,
                                                       float* __restrict__ ps) {
    int lc = threadIdx.x & 31;
    int rg = threadIdx.x >> 5;
    int cp = blockIdx.x * 32 + lc;
    int r0 = blockIdx.y * 256;
    const __half2* Y2 = (const __half2*)Y;
    int stride = Ncol >> 1;
    float sx = 0.f, sx2 = 0.f, sy = 0.f, sy2 = 0.f;
    #pragma unroll 4
    for (int i = 0; i < 32; i++) {
        int r = r0 + rg + i*8;
        float2 f = __half22float2(Y2[(size_t)r * stride + cp]);
        sx += f.x; sx2 += f.x*f.x; sy += f.y; sy2 += f.y*f.y;
    }
    __shared__ float sA[8][32], sB[8][32], sC2[8][32], sD[8][32];
    sA[rg][lc] = sx; sB[rg][lc] = sx2; sC2[rg][lc] = sy; sD[rg][lc] = sy2;
    __syncthreads();
    if (rg == 0) {
        #pragma unroll
        for (int gg = 1; gg < 8; gg++) {
            sx += sA[gg][lc]; sx2 += sB[gg][lc]; sy += sC2[gg][lc]; sy2 += sD[gg][lc];
        }
        atomicAdd(&ps[2*cp],            sx);
        atomicAdd(&ps[2*cp + 1],        sy);
        atomicAdd(&ps[Ncol + 2*cp],     sx2);
        atomicAdd(&ps[Ncol + 2*cp + 1], sy2);
    }
}

// ---------------- split-row column stats, fp32 input ----------------
// grid (Ncol/32, RG)
__global__ __launch_bounds__(256) void colstats_part_f(const float* __restrict__ Y, int Ncol,
                                                       float* __restrict__ ps) {
    int lc = threadIdx.x & 31;
    int rg = threadIdx.x >> 5;
    int c  = blockIdx.x * 32 + lc;
    int r0 = blockIdx.y * 256;
    float s = 0.f, s2 = 0.f;
    #pragma unroll 4
    for (int i = 0; i < 32; i++) {
        int r = r0 + rg + i*8;
        float v = Y[(size_t)r * Ncol + c];
        s += v; s2 += v * v;
    }
    __shared__ float sh[8][32], sh2[8][32];
    sh[rg][lc] = s; sh2[rg][lc] = s2;
    __syncthreads();
    if (rg == 0) {
        #pragma unroll
        for (int gg = 1; gg < 8; gg++) { s += sh[gg][lc]; s2 += sh2[gg][lc]; }
        atomicAdd(&ps[c],        s);
        atomicAdd(&ps[Ncol + c], s2);
    }
}

// ---------------- finalize: partial sums -> fused scale/shift ----------------
__global__ __launch_bounds__(256) void finalize_bn(const float* __restrict__ ps, int Ncol,
                                                   const float* __restrict__ gamma,
                                                   const float* __restrict__ beta,
                                                   float* __restrict__ scOut,
                                                   float* __restrict__ shOut) {
    int c = blockIdx.x * 256 + threadIdx.x;
    if (c < Ncol) {
        float mean = ps[c] * (1.0f / MM);
        float var  = ps[Ncol + c] * (1.0f / MM) - mean * mean;
        float sc   = gamma[c] * rsqrtf(var + EPSV);
        scOut[c] = sc;
        shOut[c] = beta[c] - mean * sc;
    }
}

// ---------------- fused attention (unchanged from R10) ----------------
__global__ __launch_bounds__(224, 2) void attn_kernel(const __half* __restrict__ Y,
                                                      const __half* __restrict__ Bg,
                                                      const float* __restrict__ sc1,
                                                      const float* __restrict__ sh1,
                                                      __half* __restrict__ Ohs) {
    extern __shared__ uint32_t sm[];
    float* smf = (float*)sm;
    const int QH = 0, KH = 6272, VH = 17024, BH = 27776;
    const int STAGE = 64*56;
    const int BSTG  = 112*72;
    float* uRow = smf + 25984;
    float* aq = smf + 26096; float* bq = smf + 26144;
    float* ak = smf + 26192; float* bk = smf + 26240;
    float* cv = smf + 26288; float* ev = smf + 26336;

    int t = threadIdx.x;
    int w = t >> 5, L = t & 31;
    int g = L >> 2, c = L & 3;
    int m0l = w * 16;
    int bh = blockIdx.y;
    int b = bh >> 3, h = bh & 7;
    int q0 = blockIdx.x * 112;

    uint32_t base = smem_u32(sm);
    uint32_t kBase = base + KH*2, vBase = base + VH*2, bBase = base + BH*2;
    const __half* BgRow = Bg + ((size_t)h*NN + q0) * NN;

    #define ISSUE_TILE(kt, stage) { \
        int k0i = (kt) * 64; \
        for (int idx = t; idx < 1664; idx += 224) { \
            if (idx < 768) { \
                int hv  = idx >= 384; \
                int rem = idx - hv*384; \
                int row = rem / 6, seg = rem - row*6; \
                int n = k0i + row; if (n > NN-1) n = NN-1; \
                const __half* src = Y + (size_t)(b*NN + n)*INNER + (hv ? 768 : 384) + h*HD + seg*8; \
                uint32_t dst = (hv ? vBase : kBase) + (stage)*STAGE*2 + (row*56 + seg*8)*2; \
                asm volatile("cp.async.ca.shared.global [%0], [%1], 16;" :: "r"(dst), "l"(src)); \
            } else { \
                int ib = idx - 768; \
                int row = ib >> 3, seg = ib & 7; \
                const __half* src = BgRow + (size_t)row*NN + k0i + seg*8; \
                uint32_t dst = bBase + (stage)*BSTG*2 + (row*72 + seg*8)*2; \
                asm volatile("cp.async.ca.shared.global [%0], [%1], 16;" :: "r"(dst), "l"(src)); \
            } \
        } \
        asm volatile("cp.async.commit_group;"); }

    ISSUE_TILE(0, 0);
    ISSUE_TILE(1, 1);

    for (int i = t; i < 288; i += 224) {
        int which = i / 48, d = i - which*48;
        int p = which >> 1;
        float v = (which & 1) ? sh1[p*CC + h*HD + d] : sc1[p*CC + h*HD + d];
        smf[26096 + which*48 + d] = v;
    }
    __syncthreads();

    const float scale = 0.14433756729740643f;
    const float cs = scale * 1.4426950408889634f;

    {
        int row = t >> 1, ds = (t & 1) * 24;
        const __half2* src = (const __half2*)(Y + (size_t)(b*NN + q0 + row)*INNER + h*HD + ds);
        float tpart = 0.f;
        #pragma unroll
        for (int j = 0; j < 12; j++) {
            int d = ds + 2*j;
            float2 f = __half22float2(src[j]);
            float q0f = fmaf(f.x, aq[d],   bq[d]);
            float q1f = fmaf(f.y, aq[d+1], bq[d+1]);
            tpart = fmaf(q0f, bk[d], tpart);
            tpart = fmaf(q1f, bk[d+1], tpart);
            sm[QH/2 + row*28 + ds/2 + j] = pack2(q0f*ak[d], q1f*ak[d+1]);
        }
        tpart += __shfl_xor_sync(0xffffffffu, tpart, 1);
        if ((t & 1) == 0) uRow[row] = cs * tpart;
    }
    __syncthreads();

    uint32_t qA = base + QH*2 + ((m0l + (L & 15))*56 + (L >> 4)*8)*2;
    uint32_t qa0[3], qa1[3], qa2[3], qa3[3];
    #pragma unroll
    for (int ks = 0; ks < 3; ks++)
        ldsm4(qa0[ks], qa1[ks], qa2[ks], qa3[ks], qA + ks*32);
    float u0 = uRow[m0l + g];
    float u1 = uRow[m0l + 8 + g];

    int r8 = L & 7, sel = L >> 3;
    uint32_t kB_rel = (uint32_t)((((sel >> 1)*8 + r8)*56 + (sel & 1)*8)*2);
    uint32_t vB_rel = (uint32_t)((((sel & 1)*8 + r8)*56)*2 + (sel >> 1)*16);

    int bw0 = BH/2 + (m0l + g)*36 + c;
    int bw1 = BH/2 + (m0l + 8 + g)*36 + c;

    float Oc[6][4] = {};
    float lsum0 = 0.f, lsum1 = 0.f;

    for (int kt = 0; kt < 13; kt++) {
        int k0 = kt * 64;
        uint32_t so  = (kt % 3) * STAGE*2;
        int sob = (kt % 3) * BSTG / 2;
        if (kt < 12) asm volatile("cp.async.wait_group 1;");
        else         asm volatile("cp.async.wait_group 0;");
        __syncthreads();
        if (kt + 2 < 13) { ISSUE_TILE(kt + 2, (kt + 2) % 3); }

        float Sc[8][4] = {};
        #pragma unroll
        for (int ks = 0; ks < 3; ks++) {
            #pragma unroll
            for (int nbp = 0; nbp < 4; nbp++) {
                uint32_t b00, b10, b01, b11;
                ldsm4(b00, b10, b01, b11, kBase + so + nbp*16*112 + ks*32 + kB_rel);
                mma_f16(Sc[2*nbp],   qa0[ks], qa1[ks], qa2[ks], qa3[ks], b00, b10);
                mma_f16(Sc[2*nbp+1], qa0[ks], qa1[ks], qa2[ks], qa3[ks], b01, b11);
            }
        }

        float Pv[8][4];
        #pragma unroll
        for (int nb = 0; nb < 8; nb++) {
            int kj = k0 + nb*8 + 2*c;
            float p0 = 0.f, p1 = 0.f, p2 = 0.f, p3 = 0.f;
            float2 bf0 = __half22float2(*(const __half2*)&sm[sob + bw0 + nb*4]);
            float2 bf1 = __half22float2(*(const __half2*)&sm[sob + bw1 + nb*4]);
            if (kj < NN) {
                p0 = ex2(fmaf(Sc[nb][0], cs, u0 + bf0.x));
                p2 = ex2(fmaf(Sc[nb][2], cs, u1 + bf1.x));
            }
            if (kj + 1 < NN) {
                p1 = ex2(fmaf(Sc[nb][1], cs, u0 + bf0.y));
                p3 = ex2(fmaf(Sc[nb][3], cs, u1 + bf1.y));
            }
            Pv[nb][0] = p0; Pv[nb][1] = p1; Pv[nb][2] = p2; Pv[nb][3] = p3;
            lsum0 += p0 + p1; lsum1 += p2 + p3;
        }

        #pragma unroll
        for (int ks = 0; ks < 4; ks++) {
            uint32_t a0 = pack2(Pv[2*ks][0],   Pv[2*ks][1]);
            uint32_t a1 = pack2(Pv[2*ks][2],   Pv[2*ks][3]);
            uint32_t a2 = pack2(Pv[2*ks+1][0], Pv[2*ks+1][1]);
            uint32_t a3 = pack2(Pv[2*ks+1][2], Pv[2*ks+1][3]);
            #pragma unroll
            for (int nbp = 0; nbp < 3; nbp++) {
                uint32_t b00, b10, b01, b11;
                ldsm4t(b00, b10, b01, b11, vBase + so + ks*16*112 + nbp*32 + vB_rel);
                mma_f16(Oc[2*nbp],   a0, a1, a2, a3, b00, b10);
                mma_f16(Oc[2*nbp+1], a0, a1, a2, a3, b01, b11);
            }
        }
    }
    #undef ISSUE_TILE

    lsum0 += __shfl_xor_sync(0xffffffffu, lsum0, 1);
    lsum0 += __shfl_xor_sync(0xffffffffu, lsum0, 2);
    lsum1 += __shfl_xor_sync(0xffffffffu, lsum1, 1);
    lsum1 += __shfl_xor_sync(0xffffffffu, lsum1, 2);

    float inv0 = 1.0f / lsum0;
    float inv1 = 1.0f / lsum1;
    int n0g = q0 + m0l + g, n1g = n0g + 8;
    __half2* O2 = (__half2*)Ohs;
    #pragma unroll
    for (int nb = 0; nb < 6; nb++) {
        int d = nb*8 + 2*c;
        float o00 = fmaf(Oc[nb][0]*inv0, cv[d],   ev[d]);
        float o01 = fmaf(Oc[nb][1]*inv0, cv[d+1], ev[d+1]);
        float o10 = fmaf(Oc[nb][2]*inv1, cv[d],   ev[d]);
        float o11 = fmaf(Oc[nb][3]*inv1, cv[d+1], ev[d+1]);
        O2[((size_t)(b*NN + n0g)*CC + h*HD + d) >> 1] = __floats2half2_rn(hswish(o00), hswish(o01));
        O2[((size_t)(b*NN + n1g)*CC + h*HD + d) >> 1] = __floats2half2_rn(hswish(o10), hswish(o11));
    }
}

// ---------------- final BN apply ----------------
__global__ __launch_bounds__(256) void apply_bn(const float* __restrict__ Z,
                                                const float* __restrict__ sc,
                                                const float* __restrict__ sh,
                                                float* __restrict__ out) {
    size_t base = ((size_t)blockIdx.x * 256 + threadIdx.x) * 4;
    if (base < (size_t)MM * CC) {
        float4 z = *(const float4*)(Z + base);
        int c = (int)(base % CC);
        float4 o;
        o.x = z.x * sc[c+0] + sh[c+0];
        o.y = z.y * sc[c+1] + sh[c+1];
        o.z = z.z * sc[c+2] + sh[c+2];
        o.w = z.w * sc[c+3] + sh[c+3];
        *(float4*)(out + base) = o;
    }
}

extern "C" void kernel_launch(void* const* d_in, const int* in_sizes, int n_in,
                              void* d_out, int out_size) {
    const float* x      = (const float*)d_in[0];
    const float* Wqkv   = (const float*)d_in[1];
    const float* g1     = (const float*)d_in[2];
    const float* b1     = (const float*)d_in[3];
    const float* Wproj  = (const float*)d_in[4];
    const float* g2     = (const float*)d_in[5];
    const float* b2     = (const float*)d_in[6];
    const float* biases = (const float*)d_in[7];
    float* out = (float*)d_out;

    __half *xh, *wqh, *wph, *yh, *ohsh, *bg;
    float *sc1, *sh1, *zp, *sc2, *sh2, *ps1, *ps2;
    cudaGetSymbolAddress((void**)&xh,   g_xh);
    cudaGetSymbolAddress((void**)&wqh,  g_wqh);
    cudaGetSymbolAddress((void**)&wph,  g_wph);
    cudaGetSymbolAddress((void**)&yh,   g_yh);
    cudaGetSymbolAddress((void**)&sc1,  g_sc1);
    cudaGetSymbolAddress((void**)&sh1,  g_sh1);
    cudaGetSymbolAddress((void**)&ohsh, g_ohsh);
    cudaGetSymbolAddress((void**)&zp,   g_z);
    cudaGetSymbolAddress((void**)&sc2,  g_sc2);
    cudaGetSymbolAddress((void**)&sh2,  g_sh2);
    cudaGetSymbolAddress((void**)&bg,   g_bg);
    cudaGetSymbolAddress((void**)&ps1,  g_ps1);
    cudaGetSymbolAddress((void**)&ps2,  g_ps2);

    cudaFuncSetAttribute(gemm_cp<1>, cudaFuncAttributeMaxDynamicSharedMemorySize, 61440);
    cudaFuncSetAttribute(gemm_cp<0>, cudaFuncAttributeMaxDynamicSharedMemorySize, 61440);
    cudaFuncSetAttribute(attn_kernel, cudaFuncAttributeMaxDynamicSharedMemorySize, 105536);

    int n4all = N4_X + N4_WQ + N4_WP;
    zero_ps<<<(2*INNER + 2*CC + 255)/256, 256>>>();
    f2h_all<<<(n4all + 255)/256, 256>>>(x, Wqkv, Wproj);
    bias_expand<<<dim3(NN, HH), 256>>>(biases);

    gemm_cp<1><<<dim3(INNER/128, MM/128), 256, 61440>>>(xh, wqh, yh, INNER);
    colstats_part_h<<<dim3(INNER/64, RG), 256>>>(yh, INNER, ps1);
    finalize_bn<<<(INNER + 255)/256, 256>>>(ps1, INNER, g1, b1, sc1, sh1);
    attn_kernel<<<dim3(7, BB*HH), 224, 105536>>>(yh, bg, sc1, sh1, ohsh);
    gemm_cp<0><<<dim3(CC/128, MM/128), 256, 61440>>>(ohsh, wph, zp, CC);
    colstats_part_f<<<dim3(CC/32, RG), 256>>>(zp, CC, ps2);
    finalize_bn<<<(CC + 255)/256, 256>>>(ps2, CC, g2, b2, sc2, sh2);
    apply_bn<<<(MM*CC/4 + 255)/256, 256>>>(zp, sc2, sh2, out);
}

// round 12
// speedup vs baseline: 3.0422x; 1.0020x over previous
#include <cuda_runtime.h>
#include <cuda_fp16.h>
#include <math.h>
#include <stdint.h>

#define BB 16
#define NN 784
#define CC 384
#define HH 8
#define HD 48
#define INNER 1152
#define MM (BB*NN)          // 12544
#define EPSV 1e-5f

// ---------------- scratch ----------------
__device__ __half g_xh[(size_t)MM * CC];
__device__ __half g_wqh[(size_t)INNER * CC];
__device__ __half g_wph[(size_t)CC * CC];
__device__ __half g_yh[(size_t)MM * INNER];     // qkv pre-norm, fp16 (28.9 MB)
__device__ float  g_sc1[INNER];
__device__ float  g_sh1[INNER];
__device__ __half g_ohsh[(size_t)MM * CC];      // hardswish(attn out), fp16
__device__ float  g_z[(size_t)MM * CC];         // proj pre-norm, fp32
__device__ float  g_sc2[CC];
__device__ float  g_sh2[CC];
__device__ __half g_bg[(size_t)HH * NN * NN + 64];   // pre-gathered bias*log2e, fp16
__device__ float  g_ps1[2*INNER];               // BN1 partial sums (sum | sumsq)
__device__ float  g_ps2[2*CC];                  // BN2 partial sums

// ---------------- helpers ----------------
__device__ __forceinline__ uint32_t pack2(float a, float b) {
    __half2 h = __floats2half2_rn(a, b);
    return *reinterpret_cast<uint32_t*>(&h);
}
__device__ __forceinline__ uint32_t smem_u32(const void* p) {
    return (uint32_t)__cvta_generic_to_shared(p);
}
__device__ __forceinline__ float ex2(float x) {        // MUFU.EX2
    float r;
    asm("ex2.approx.f32 %0, %1;" : "=f"(r) : "f"(x));
    return r;
}
__device__ __forceinline__ void mma_f16(float* c,
        uint32_t a0, uint32_t a1, uint32_t a2, uint32_t a3,
        uint32_t b0, uint32_t b1) {
    asm volatile("mma.sync.aligned.m16n8k16.row.col.f32.f16.f16.f32 "
                 "{%0,%1,%2,%3},{%4,%5,%6,%7},{%8,%9},{%0,%1,%2,%3};"
                 : "+f"(c[0]), "+f"(c[1]), "+f"(c[2]), "+f"(c[3])
                 : "r"(a0), "r"(a1), "r"(a2), "r"(a3), "r"(b0), "r"(b1));
}
__device__ __forceinline__ void ldsm4(uint32_t& r0, uint32_t& r1, uint32_t& r2, uint32_t& r3, uint32_t a) {
    asm volatile("ldmatrix.sync.aligned.m8n8.x4.shared.b16 {%0,%1,%2,%3}, [%4];"
                 : "=r"(r0),"=r"(r1),"=r"(r2),"=r"(r3) : "r"(a));
}
__device__ __forceinline__ void ldsm4t(uint32_t& r0, uint32_t& r1, uint32_t& r2, uint32_t& r3, uint32_t a) {
    asm volatile("ldmatrix.sync.aligned.m8n8.x4.trans.shared.b16 {%0,%1,%2,%3}, [%4];"
                 : "=r"(r0),"=r"(r1),"=r"(r2),"=r"(r3) : "r"(a));
}
__device__ __forceinline__ float hswish(float v) {
    return v * fminf(fmaxf(v + 3.f, 0.f), 6.f) * (1.0f/6.0f);
}

// ---------------- fp32->fp16 convert + zero BN partials, one launch ----------------
#define N4_X   (MM*CC/4)
#define N4_WQ  (INNER*CC/4)
#define N4_WP  (CC*CC/4)
#define N4_ALL (N4_X + N4_WQ + N4_WP)
__global__ __launch_bounds__(256) void f2h_all(const float* __restrict__ x,
                                               const float* __restrict__ wq,
                                               const float* __restrict__ wp) {
    int i = blockIdx.x * 256 + threadIdx.x;
    if (i >= N4_ALL) {
        int j = i - N4_ALL;
        if (j < 2*INNER) g_ps1[j] = 0.f;
        else if (j < 2*INNER + 2*CC) g_ps2[j - 2*INNER] = 0.f;
        return;
    }
    const float* in; __half* out; int idx;
    if (i < N4_X)              { in = x;  out = g_xh;  idx = i; }
    else if (i < N4_X + N4_WQ) { in = wq; out = g_wqh; idx = i - N4_X; }
    else                       { in = wp; out = g_wph; idx = i - N4_X - N4_WQ; }
    float4 v = ((const float4*)in)[idx];
    __half2* o = (__half2*)out;
    o[2*idx]   = __floats2half2_rn(v.x, v.y);
    o[2*idx+1] = __floats2half2_rn(v.z, v.w);
}

// ---------------- pre-gather bias ----------------
__global__ __launch_bounds__(256) void bias_expand(const float* __restrict__ biases) {
    int qi = blockIdx.x;
    int h  = blockIdx.y;
    __shared__ float br[NN];
    for (int i = threadIdx.x; i < NN; i += 256)
        br[i] = biases[h*NN + i] * 1.4426950408889634f;
    __syncthreads();
    int xi = qi / 28, yi = qi - xi*28;
    __half* dst = g_bg + ((size_t)h*NN + qi) * NN;
    for (int kj = threadIdx.x; kj < NN; kj += 256) {
        int xj = kj / 28, yj = kj - xj*28;
        dst[kj] = __float2half_rn(br[abs(xi-xj)*28 + abs(yi-yj)]);
    }
}

// ---------------- cp.async pipelined fp16 GEMM NT (K=384) + fused BN column stats ----------------
// Stats computed on the STORED values (fp16-rounded when OUTH=1) and
// atomically accumulated into ps[col] (sum) / ps[Ncol+col] (sumsq).
template<int OUTH>
__global__ __launch_bounds__(256) void gemm_cp(const __half* __restrict__ A,
                                               const __half* __restrict__ Bw,
                                               void* __restrict__ C, int Nn,
                                               float* __restrict__ ps) {
    extern __shared__ __half hs[];          // [3][2][128*40]
    const int STG = 128*40;
    int t = threadIdx.x;
    int w = t >> 5, L = t & 31;
    int g = L >> 2, c = L & 3;
    int wm = w & 3, wn = w >> 2;
    int m0 = blockIdx.y * 128, n0 = blockIdx.x * 128;

    int id0 = t, id1 = t + 256;
    int ra0 = id0 >> 2, oa0 = (id0 & 3) * 8;
    int ra1 = id1 >> 2, oa1 = (id1 & 3) * 8;
    const __half* Ap0 = A  + (size_t)(m0 + ra0) * 384 + oa0;
    const __half* Ap1 = A  + (size_t)(m0 + ra1) * 384 + oa1;
    const __half* Bp0 = Bw + (size_t)(n0 + ra0) * 384 + oa0;
    const __half* Bp1 = Bw + (size_t)(n0 + ra1) * 384 + oa1;

    uint32_t base = smem_u32(hs);
    uint32_t dA0 = base + (ra0*40 + oa0)*2;
    uint32_t dA1 = base + (ra1*40 + oa1)*2;
    uint32_t dB0 = base + (STG + ra0*40 + oa0)*2;
    uint32_t dB1 = base + (STG + ra1*40 + oa1)*2;

    int r8 = L & 7, sel = L >> 3;
    uint32_t aAddr = base + ((wm*32 + (L & 15))*40 + (L >> 4)*8)*2;
    uint32_t bAddr = base + STG*2 + ((wn*64 + (sel>>1)*8 + r8)*40 + (sel&1)*8)*2;

    #define ISSUE(st, kc) { \
        int ko = (kc) * 32; uint32_t so = (st) * (2*STG*2); \
        asm volatile("cp.async.ca.shared.global [%0], [%1], 16;" :: "r"(dA0+so), "l"(Ap0+ko)); \
        asm volatile("cp.async.ca.shared.global [%0], [%1], 16;" :: "r"(dA1+so), "l"(Ap1+ko)); \
        asm volatile("cp.async.ca.shared.global [%0], [%1], 16;" :: "r"(dB0+so), "l"(Bp0+ko)); \
        asm volatile("cp.async.ca.shared.global [%0], [%1], 16;" :: "r"(dB1+so), "l"(Bp1+ko)); \
        asm volatile("cp.async.commit_group;"); }

    float acc[2][8][4] = {};
    ISSUE(0, 0); ISSUE(1, 1);

    for (int kc = 0; kc < 12; kc++) {
        if (kc < 11) asm volatile("cp.async.wait_group 1;");
        else         asm volatile("cp.async.wait_group 0;");
        __syncthreads();
        if (kc + 2 < 12) { ISSUE((kc+2)%3, kc+2); }
        uint32_t so = (kc % 3) * (2*STG*2);
        #pragma unroll
        for (int ks = 0; ks < 2; ks++) {
            uint32_t a0[2], a1[2], a2[2], a3[2];
            #pragma unroll
            for (int i = 0; i < 2; i++)
                ldsm4(a0[i], a1[i], a2[i], a3[i], aAddr + so + i*16*80 + ks*32);
            #pragma unroll
            for (int nbp = 0; nbp < 4; nbp++) {
                uint32_t b00, b10, b01, b11;
                ldsm4(b00, b10, b01, b11, bAddr + so + nbp*16*80 + ks*32);
                #pragma unroll
                for (int i = 0; i < 2; i++) {
                    mma_f16(acc[i][2*nbp],   a0[i], a1[i], a2[i], a3[i], b00, b10);
                    mma_f16(acc[i][2*nbp+1], a0[i], a1[i], a2[i], a3[i], b01, b11);
                }
            }
        }
    }
    #undef ISSUE

    // store outputs (values used for stats = stored values)
    float sv[8][4];   // per-nb: rows (r, r+8) x cols (col, col+1), rounded if OUTH
    #pragma unroll
    for (int i = 0; i < 2; i++) {
        int row = m0 + wm*32 + i*16 + g;
        #pragma unroll
        for (int nb = 0; nb < 8; nb++) {
            int col = n0 + wn*64 + nb*8 + 2*c;
            if (OUTH) {
                __half2 h0 = __floats2half2_rn(acc[i][nb][0], acc[i][nb][1]);
                __half2 h1 = __floats2half2_rn(acc[i][nb][2], acc[i][nb][3]);
                __half2* Ch = (__half2*)C;
                Ch[((size_t)row*Nn + col) >> 1]     = h0;
                Ch[((size_t)(row+8)*Nn + col) >> 1] = h1;
                float2 f0 = __half22float2(h0);
                float2 f1 = __half22float2(h1);
                if (i == 0) { sv[nb][0]=f0.x; sv[nb][1]=f0.y; sv[nb][2]=f1.x; sv[nb][3]=f1.y; }
                else        { sv[nb][0]+=0.f; // keep shape; accumulate below
                              sv[nb][0]=sv[nb][0]; }
                if (i == 1) { sv[nb][0]+=0.f; }
                // handled by stats accumulation below instead
            } else {
                float* Cf = (float*)C;
                *(float2*)(Cf + (size_t)row*Nn + col)     = make_float2(acc[i][nb][0], acc[i][nb][1]);
                *(float2*)(Cf + (size_t)(row+8)*Nn + col) = make_float2(acc[i][nb][2], acc[i][nb][3]);
            }
        }
    }

    // ---- fused BN column stats ----
    // local per-column sums over this thread's 4 rows
    float s0[8], s1[8], q0[8], q1[8];
    #pragma unroll
    for (int nb = 0; nb < 8; nb++) { s0[nb]=0.f; s1[nb]=0.f; q0[nb]=0.f; q1[nb]=0.f; }
    #pragma unroll
    for (int i = 0; i < 2; i++) {
        #pragma unroll
        for (int nb = 0; nb < 8; nb++) {
            float v0, v1, v2, v3;
            if (OUTH) {
                __half2 h0 = __floats2half2_rn(acc[i][nb][0], acc[i][nb][1]);
                __half2 h1 = __floats2half2_rn(acc[i][nb][2], acc[i][nb][3]);
                float2 f0 = __half22float2(h0), f1 = __half22float2(h1);
                v0=f0.x; v1=f0.y; v2=f1.x; v3=f1.y;
            } else {
                v0=acc[i][nb][0]; v1=acc[i][nb][1]; v2=acc[i][nb][2]; v3=acc[i][nb][3];
            }
            s0[nb] += v0 + v2;  q0[nb] += v0*v0 + v2*v2;
            s1[nb] += v1 + v3;  q1[nb] += v1*v1 + v3*v3;
        }
    }
    // reduce across g lanes (masks 4,8,16) — same columns, different rows
    #pragma unroll
    for (int nb = 0; nb < 8; nb++) {
        #pragma unroll
        for (int m = 4; m <= 16; m <<= 1) {
            s0[nb] += __shfl_xor_sync(0xffffffffu, s0[nb], m);
            s1[nb] += __shfl_xor_sync(0xffffffffu, s1[nb], m);
            q0[nb] += __shfl_xor_sync(0xffffffffu, q0[nb], m);
            q1[nb] += __shfl_xor_sync(0xffffffffu, q1[nb], m);
        }
    }
    // smem accumulate across the 4 m-warps (wm)
    float* cs_  = (float*)hs;          // [128] col sums
    float* cs2_ = (float*)hs + 128;    // [128] col sumsq
    __syncthreads();                   // pipeline smem reads done
    if (t < 128) { cs_[t] = 0.f; cs2_[t] = 0.f; }
    __syncthreads();
    if (g == 0) {
        #pragma unroll
        for (int nb = 0; nb < 8; nb++) {
            int lc0 = wn*64 + nb*8 + 2*c;
            atomicAdd(&cs_[lc0],      s0[nb]);
            atomicAdd(&cs_[lc0 + 1],  s1[nb]);
            atomicAdd(&cs2_[lc0],     q0[nb]);
            atomicAdd(&cs2_[lc0 + 1], q1[nb]);
        }
    }
    __syncthreads();
    if (t < 128) {
        int gcol = n0 + t;
        atomicAdd(&ps[gcol],      cs_[t]);
        atomicAdd(&ps[Nn + gcol], cs2_[t]);
    }
}

// ---------------- finalize: partial sums -> fused scale/shift ----------------
__global__ __launch_bounds__(256) void finalize_bn(const float* __restrict__ ps, int Ncol,
                                                   const float* __restrict__ gamma,
                                                   const float* __restrict__ beta,
                                                   float* __restrict__ scOut,
                                                   float* __restrict__ shOut) {
    int c = blockIdx.x * 256 + threadIdx.x;
    if (c < Ncol) {
        float mean = ps[c] * (1.0f / MM);
        float var  = ps[Ncol + c] * (1.0f / MM) - mean * mean;
        float sc   = gamma[c] * rsqrtf(var + EPSV);
        scOut[c] = sc;
        shOut[c] = beta[c] - mean * sc;
    }
}

// ---------------- fused attention (unchanged) ----------------
__global__ __launch_bounds__(224, 2) void attn_kernel(const __half* __restrict__ Y,
                                                      const __half* __restrict__ Bg,
                                                      const float* __restrict__ sc1,
                                                      const float* __restrict__ sh1,
                                                      __half* __restrict__ Ohs) {
    extern __shared__ uint32_t sm[];
    float* smf = (float*)sm;
    const int QH = 0, KH = 6272, VH = 17024, BH = 27776;
    const int STAGE = 64*56;
    const int BSTG  = 112*72;
    float* uRow = smf + 25984;
    float* aq = smf + 26096; float* bq = smf + 26144;
    float* ak = smf + 26192; float* bk = smf + 26240;
    float* cv = smf + 26288; float* ev = smf + 26336;

    int t = threadIdx.x;
    int w = t >> 5, L = t & 31;
    int g = L >> 2, c = L & 3;
    int m0l = w * 16;
    int bh = blockIdx.y;
    int b = bh >> 3, h = bh & 7;
    int q0 = blockIdx.x * 112;

    uint32_t base = smem_u32(sm);
    uint32_t kBase = base + KH*2, vBase = base + VH*2, bBase = base + BH*2;
    const __half* BgRow = Bg + ((size_t)h*NN + q0) * NN;

    #define ISSUE_TILE(kt, stage) { \
        int k0i = (kt) * 64; \
        for (int idx = t; idx < 1664; idx += 224) { \
            if (idx < 768) { \
                int hv  = idx >= 384; \
                int rem = idx - hv*384; \
                int row = rem / 6, seg = rem - row*6; \
                int n = k0i + row; if (n > NN-1) n = NN-1; \
                const __half* src = Y + (size_t)(b*NN + n)*INNER + (hv ? 768 : 384) + h*HD + seg*8; \
                uint32_t dst = (hv ? vBase : kBase) + (stage)*STAGE*2 + (row*56 + seg*8)*2; \
                asm volatile("cp.async.ca.shared.global [%0], [%1], 16;" :: "r"(dst), "l"(src)); \
            } else { \
                int ib = idx - 768; \
                int row = ib >> 3, seg = ib & 7; \
                const __half* src = BgRow + (size_t)row*NN + k0i + seg*8; \
                uint32_t dst = bBase + (stage)*BSTG*2 + (row*72 + seg*8)*2; \
                asm volatile("cp.async.ca.shared.global [%0], [%1], 16;" :: "r"(dst), "l"(src)); \
            } \
        } \
        asm volatile("cp.async.commit_group;"); }

    ISSUE_TILE(0, 0);
    ISSUE_TILE(1, 1);

    for (int i = t; i < 288; i += 224) {
        int which = i / 48, d = i - which*48;
        int p = which >> 1;
        float v = (which & 1) ? sh1[p*CC + h*HD + d] : sc1[p*CC + h*HD + d];
        smf[26096 + which*48 + d] = v;
    }
    __syncthreads();

    const float scale = 0.14433756729740643f;
    const float cs = scale * 1.4426950408889634f;

    {
        int row = t >> 1, ds = (t & 1) * 24;
        const __half2* src = (const __half2*)(Y + (size_t)(b*NN + q0 + row)*INNER + h*HD + ds);
        float tpart = 0.f;
        #pragma unroll
        for (int j = 0; j < 12; j++) {
            int d = ds + 2*j;
            float2 f = __half22float2(src[j]);
            float q0f = fmaf(f.x, aq[d],   bq[d]);
            float q1f = fmaf(f.y, aq[d+1], bq[d+1]);
            tpart = fmaf(q0f, bk[d], tpart);
            tpart = fmaf(q1f, bk[d+1], tpart);
            sm[QH/2 + row*28 + ds/2 + j] = pack2(q0f*ak[d], q1f*ak[d+1]);
        }
        tpart += __shfl_xor_sync(0xffffffffu, tpart, 1);
        if ((t & 1) == 0) uRow[row] = cs * tpart;
    }
    __syncthreads();

    uint32_t qA = base + QH*2 + ((m0l + (L & 15))*56 + (L >> 4)*8)*2;
    uint32_t qa0[3], qa1[3], qa2[3], qa3[3];
    #pragma unroll
    for (int ks = 0; ks < 3; ks++)
        ldsm4(qa0[ks], qa1[ks], qa2[ks], qa3[ks], qA + ks*32);
    float u0 = uRow[m0l + g];
    float u1 = uRow[m0l + 8 + g];

    int r8 = L & 7, sel = L >> 3;
    uint32_t kB_rel = (uint32_t)((((sel >> 1)*8 + r8)*56 + (sel & 1)*8)*2);
    uint32_t vB_rel = (uint32_t)((((sel & 1)*8 + r8)*56)*2 + (sel >> 1)*16);

    int bw0 = BH/2 + (m0l + g)*36 + c;
    int bw1 = BH/2 + (m0l + 8 + g)*36 + c;

    float Oc[6][4] = {};
    float lsum0 = 0.f, lsum1 = 0.f;

    for (int kt = 0; kt < 13; kt++) {
        int k0 = kt * 64;
        uint32_t so  = (kt % 3) * STAGE*2;
        int sob = (kt % 3) * BSTG / 2;
        if (kt < 12) asm volatile("cp.async.wait_group 1;");
        else         asm volatile("cp.async.wait_group 0;");
        __syncthreads();
        if (kt + 2 < 13) { ISSUE_TILE(kt + 2, (kt + 2) % 3); }

        float Sc[8][4] = {};
        #pragma unroll
        for (int ks = 0; ks < 3; ks++) {
            #pragma unroll
            for (int nbp = 0; nbp < 4; nbp++) {
                uint32_t b00, b10, b01, b11;
                ldsm4(b00, b10, b01, b11, kBase + so + nbp*16*112 + ks*32 + kB_rel);
                mma_f16(Sc[2*nbp],   qa0[ks], qa1[ks], qa2[ks], qa3[ks], b00, b10);
                mma_f16(Sc[2*nbp+1], qa0[ks], qa1[ks], qa2[ks], qa3[ks], b01, b11);
            }
        }

        float Pv[8][4];
        #pragma unroll
        for (int nb = 0; nb < 8; nb++) {
            int kj = k0 + nb*8 + 2*c;
            float p0 = 0.f, p1 = 0.f, p2 = 0.f, p3 = 0.f;
            float2 bf0 = __half22float2(*(const __half2*)&sm[sob + bw0 + nb*4]);
            float2 bf1 = __half22float2(*(const __half2*)&sm[sob + bw1 + nb*4]);
            if (kj < NN) {
                p0 = ex2(fmaf(Sc[nb][0], cs, u0 + bf0.x));
                p2 = ex2(fmaf(Sc[nb][2], cs, u1 + bf1.x));
            }
            if (kj + 1 < NN) {
                p1 = ex2(fmaf(Sc[nb][1], cs, u0 + bf0.y));
                p3 = ex2(fmaf(Sc[nb][3], cs, u1 + bf1.y));
            }
            Pv[nb][0] = p0; Pv[nb][1] = p1; Pv[nb][2] = p2; Pv[nb][3] = p3;
            lsum0 += p0 + p1; lsum1 += p2 + p3;
        }

        #pragma unroll
        for (int ks = 0; ks < 4; ks++) {
            uint32_t a0 = pack2(Pv[2*ks][0],   Pv[2*ks][1]);
            uint32_t a1 = pack2(Pv[2*ks][2],   Pv[2*ks][3]);
            uint32_t a2 = pack2(Pv[2*ks+1][0], Pv[2*ks+1][1]);
            uint32_t a3 = pack2(Pv[2*ks+1][2], Pv[2*ks+1][3]);
            #pragma unroll
            for (int nbp = 0; nbp < 3; nbp++) {
                uint32_t b00, b10, b01, b11;
                ldsm4t(b00, b10, b01, b11, vBase + so + ks*16*112 + nbp*32 + vB_rel);
                mma_f16(Oc[2*nbp],   a0, a1, a2, a3, b00, b10);
                mma_f16(Oc[2*nbp+1], a0, a1, a2, a3, b01, b11);
            }
        }
    }
    #undef ISSUE_TILE

    lsum0 += __shfl_xor_sync(0xffffffffu, lsum0, 1);
    lsum0 += __shfl_xor_sync(0xffffffffu, lsum0, 2);
    lsum1 += __shfl_xor_sync(0xffffffffu, lsum1, 1);
    lsum1 += __shfl_xor_sync(0xffffffffu, lsum1, 2);

    float inv0 = 1.0f / lsum0;
    float inv1 = 1.0f / lsum1;
    int n0g = q0 + m0l + g, n1g = n0g + 8;
    __half2* O2 = (__half2*)Ohs;
    #pragma unroll
    for (int nb = 0; nb < 6; nb++) {
        int d = nb*8 + 2*c;
        float o00 = fmaf(Oc[nb][0]*inv0, cv[d],   ev[d]);
        float o01 = fmaf(Oc[nb][1]*inv0, cv[d+1], ev[d+1]);
        float o10 = fmaf(Oc[nb][2]*inv1, cv[d],   ev[d]);
        float o11 = fmaf(Oc[nb][3]*inv1, cv[d+1], ev[d+1]);
        O2[((size_t)(b*NN + n0g)*CC + h*HD + d) >> 1] = __floats2half2_rn(hswish(o00), hswish(o01));
        O2[((size_t)(b*NN + n1g)*CC + h*HD + d) >> 1] = __floats2half2_rn(hswish(o10), hswish(o11));
    }
}

// ---------------- final BN apply ----------------
__global__ __launch_bounds__(256) void apply_bn(const float* __restrict__ Z,
                                                const float* __restrict__ sc,
                                                const float* __restrict__ sh,
                                                float* __restrict__ out) {
    size_t base = ((size_t)blockIdx.x * 256 + threadIdx.x) * 4;
    if (base < (size_t)MM * CC) {
        float4 z = *(const float4*)(Z + base);
        int c = (int)(base % CC);
        float4 o;
        o.x = z.x * sc[c+0] + sh[c+0];
        o.y = z.y * sc[c+1] + sh[c+1];
        o.z = z.z * sc[c+2] + sh[c+2];
        o.w = z.w * sc[c+3] + sh[c+3];
        *(float4*)(out + base) = o;
    }
}

extern "C" void kernel_launch(void* const* d_in, const int* in_sizes, int n_in,
                              void* d_out, int out_size) {
    const float* x      = (const float*)d_in[0];
    const float* Wqkv   = (const float*)d_in[1];
    const float* g1     = (const float*)d_in[2];
    const float* b1     = (const float*)d_in[3];
    const float* Wproj  = (const float*)d_in[4];
    const float* g2     = (const float*)d_in[5];
    const float* b2     = (const float*)d_in[6];
    const float* biases = (const float*)d_in[7];
    float* out = (float*)d_out;

    __half *xh, *wqh, *wph, *yh, *ohsh, *bg;
    float *sc1, *sh1, *zp, *sc2, *sh2, *ps1, *ps2;
    cudaGetSymbolAddress((void**)&xh,   g_xh);
    cudaGetSymbolAddress((void**)&wqh,  g_wqh);
    cudaGetSymbolAddress((void**)&wph,  g_wph);
    cudaGetSymbolAddress((void**)&yh,   g_yh);
    cudaGetSymbolAddress((void**)&sc1,  g_sc1);
    cudaGetSymbolAddress((void**)&sh1,  g_sh1);
    cudaGetSymbolAddress((void**)&ohsh, g_ohsh);
    cudaGetSymbolAddress((void**)&zp,   g_z);
    cudaGetSymbolAddress((void**)&sc2,  g_sc2);
    cudaGetSymbolAddress((void**)&sh2,  g_sh2);
    cudaGetSymbolAddress((void**)&bg,   g_bg);
    cudaGetSymbolAddress((void**)&ps1,  g_ps1);
    cudaGetSymbolAddress((void**)&ps2,  g_ps2);

    cudaFuncSetAttribute(gemm_cp<1>, cudaFuncAttributeMaxDynamicSharedMemorySize, 61440);
    cudaFuncSetAttribute(gemm_cp<0>, cudaFuncAttributeMaxDynamicSharedMemorySize, 61440);
    cudaFuncSetAttribute(attn_kernel, cudaFuncAttributeMaxDynamicSharedMemorySize, 105536);

    int nthreads = N4_ALL + 2*INNER + 2*CC;
    f2h_all<<<(nthreads + 255)/256, 256>>>(x, Wqkv, Wproj);
    bias_expand<<<dim3(NN, HH), 256>>>(biases);

    gemm_cp<1><<<dim3(INNER/128, MM/128), 256, 61440>>>(xh, wqh, yh, INNER, ps1);
    finalize_bn<<<(INNER + 255)/256, 256>>>(ps1, INNER, g1, b1, sc1, sh1);
    attn_kernel<<<dim3(7, BB*HH), 224, 105536>>>(yh, bg, sc1, sh1, ohsh);
    gemm_cp<0><<<dim3(CC/128, MM/128), 256, 61440>>>(ohsh, wph, zp, CC, ps2);
    finalize_bn<<<(CC + 255)/256, 256>>>(ps2, CC, g2, b2, sc2, sh2);
    apply_bn<<<(MM*CC/4 + 255)/256, 256>>>(zp, sc2, sh2, out);
}